// round 7
// baseline (speedup 1.0000x reference)
#include <cuda_runtime.h>
#include <cuda_bf16.h>
#include <cstdint>
#include <cstddef>

// Problem constants
#define BB 4
#define SS 2048
#define DD 1024
#define HH 16
#define DKK 64
#define FF 4096
#define MM (BB*SS)          // 8192 rows

// ---------------------------------------------------------------------------
// Scratch (no allocations allowed -> __device__ globals)
// ---------------------------------------------------------------------------
__device__ float g_proj[(size_t)MM*DD];
__device__ float g_x1  [(size_t)MM*DD];
__device__ float g_ff2 [(size_t)MM*DD];

// split bf16 buffers
__device__ unsigned short g_ax  [(size_t)MM*3*DD];   // x      (hi,hi,lo)
__device__ unsigned short g_qs  [(size_t)MM*3*DD];   // q*1/8  (hi,hi,lo)
__device__ unsigned short g_ks  [(size_t)MM*3*DD];   // k      (hi,lo,hi)
__device__ unsigned short g_vs  [(size_t)MM*2*DD];   // v      (hi | lo)
__device__ unsigned short g_aatt[(size_t)MM*3*DD];   // attn out (hi,hi,lo)
__device__ unsigned short g_ax1 [(size_t)MM*3*DD];   // x1     (hi,hi,lo)
__device__ unsigned short g_aff1[(size_t)MM*3*FF];   // relu(ff1) (hi,hi,lo)
__device__ unsigned short g_wq  [(size_t)DD*3*DD];
__device__ unsigned short g_wk  [(size_t)DD*3*DD];
__device__ unsigned short g_wv  [(size_t)DD*3*DD];
__device__ unsigned short g_wo  [(size_t)DD*3*DD];
__device__ unsigned short g_w1  [(size_t)FF*3*DD];   // [N=F, 3K=3*D]
__device__ unsigned short g_w2  [(size_t)DD*3*FF];   // [N=D, 3K=3*F]

// ---------------------------------------------------------------------------
// Helpers (family-portable PTX only: cp.async / ldmatrix / mma.sync)
// ---------------------------------------------------------------------------
__device__ __forceinline__ uint32_t smem_u32(const void* p) {
    uint32_t a;
    asm("{ .reg .u64 t; cvta.to.shared.u64 t, %1; cvt.u32.u64 %0, t; }"
        : "=r"(a) : "l"(p));
    return a;
}

__device__ __forceinline__ void cp16(uint32_t dst, const void* src) {
    asm volatile("cp.async.cg.shared.global [%0], [%1], 16;" :: "r"(dst), "l"(src));
}

#define CP_COMMIT() asm volatile("cp.async.commit_group;")
#define CP_WAIT2()  asm volatile("cp.async.wait_group 2;" ::: "memory")

#define LDSM4(r0, r1, r2, r3, addr) \
    asm volatile("ldmatrix.sync.aligned.m8n8.x4.shared.b16 {%0,%1,%2,%3}, [%4];" \
        : "=r"(r0), "=r"(r1), "=r"(r2), "=r"(r3) : "r"(addr))

#define LDSM4T(r0, r1, r2, r3, addr) \
    asm volatile("ldmatrix.sync.aligned.m8n8.x4.trans.shared.b16 {%0,%1,%2,%3}, [%4];" \
        : "=r"(r0), "=r"(r1), "=r"(r2), "=r"(r3) : "r"(addr))

#define MMA16816(d, a, b0v, b1v) \
    asm volatile("mma.sync.aligned.m16n8k16.row.col.f32.bf16.bf16.f32 " \
        "{%0,%1,%2,%3}, {%4,%5,%6,%7}, {%8,%9}, {%0,%1,%2,%3};" \
        : "+f"((d)[0]), "+f"((d)[1]), "+f"((d)[2]), "+f"((d)[3]) \
        : "r"((a)[0]), "r"((a)[1]), "r"((a)[2]), "r"((a)[3]), "r"(b0v), "r"(b1v))

__device__ __forceinline__ unsigned short f2bf_bits(float f) {
    __nv_bfloat16 h = __float2bfloat16(f);
    return *reinterpret_cast<unsigned short*>(&h);
}
__device__ __forceinline__ void bfsplit(float x, unsigned short& h, unsigned short& l) {
    h = f2bf_bits(x);
    __nv_bfloat16 hb = *reinterpret_cast<__nv_bfloat16*>(&h);
    l = f2bf_bits(x - __bfloat162float(hb));
}

// ---------------------------------------------------------------------------
// fp32 -> (hi,hi,lo) bf16 K-expansion for activations. A''[m, 3K].
// ---------------------------------------------------------------------------
__global__ __launch_bounds__(256) void convert_a_kernel(
    const float* __restrict__ X, unsigned short* __restrict__ A, int K)
{
    size_t idx = (size_t)blockIdx.x * blockDim.x + threadIdx.x;
    size_t total = (size_t)MM * K / 4;
    if (idx >= total) return;
    size_t e = idx * 4;
    size_t m = e / K;
    int k = (int)(e % K);
    float4 v = *(const float4*)(X + e);
    unsigned short h0, h1, h2, h3, l0, l1, l2, l3;
    bfsplit(v.x, h0, l0); bfsplit(v.y, h1, l1);
    bfsplit(v.z, h2, l2); bfsplit(v.w, h3, l3);
    uint2 hp = make_uint2((uint32_t)h0 | ((uint32_t)h1 << 16),
                          (uint32_t)h2 | ((uint32_t)h3 << 16));
    uint2 lp = make_uint2((uint32_t)l0 | ((uint32_t)l1 << 16),
                          (uint32_t)l2 | ((uint32_t)l3 << 16));
    size_t ob = m * (size_t)(3 * K);
    *(uint2*)(A + ob + k)         = hp;
    *(uint2*)(A + ob + K + k)     = hp;
    *(uint2*)(A + ob + 2 * K + k) = lp;
}

// ---------------------------------------------------------------------------
// W[K,N] fp32 -> B''[N, 3K] bf16 with (hi, lo, hi) layout (transposed).
// ---------------------------------------------------------------------------
__global__ __launch_bounds__(256) void convert_w_kernel(
    const float* __restrict__ W, unsigned short* __restrict__ Bm, int K, int N)
{
    __shared__ float tile[32][33];
    const int n0 = blockIdx.x * 32;
    const int k0 = blockIdx.y * 32;
    for (int i = threadIdx.y; i < 32; i += 8)
        tile[i][threadIdx.x] = W[(size_t)(k0 + i) * N + n0 + threadIdx.x];
    __syncthreads();
    for (int i = threadIdx.y; i < 32; i += 8) {
        const int n = n0 + i;
        const int k = k0 + threadIdx.x;
        unsigned short h, l;
        bfsplit(tile[threadIdx.x][i], h, l);
        size_t ob = (size_t)n * (3 * K);
        Bm[ob + k]         = h;
        Bm[ob + K + k]     = l;
        Bm[ob + 2 * K + k] = h;
    }
}

// ---------------------------------------------------------------------------
// mma.sync bf16 GEMM: BM=BN=128, BK=32, 3-stage cp.async, 256 threads
// (8 warps 2x4, warp tile 64x32). Proven round-5 inner loop.
// Epilogue modes:
//   0: fp32 C = acc + bias
//   1: relu -> split (hi,hi,lo) into Cs[m][3N]
//   2: (acc+bias)*0.125 -> split (hi,hi,lo)   [Q]
//   3: split (hi,lo,hi)                        [K]
//   4: split (hi | lo) into Cs[m][2N]          [V]
// ---------------------------------------------------------------------------
#define BK 32
#define NSTAGE 3
#define ROWB 80
#define B_OFF (128*ROWB)
#define STG_B (2*B_OFF)
#define GEMM_SMEM (NSTAGE*STG_B)    // 61440

__global__ __launch_bounds__(256) void mma_gemm_kernel(
    const unsigned short* __restrict__ Au, const unsigned short* __restrict__ Bu,
    const float* __restrict__ bias, float* __restrict__ Cf,
    unsigned short* __restrict__ Cs, int N, int K3, int mode)
{
    extern __shared__ char smem[];
    const uint32_t sb = smem_u32(smem);
    const int tid = threadIdx.x;
    const int wid = tid >> 5, lane = tid & 31;
    const int wm = wid >> 2, wn = wid & 3;
    const int mb = blockIdx.y, nb = blockIdx.x;

    const int r0 = tid >> 2, cc = tid & 3;
    const unsigned short* aS = Au + ((size_t)(mb * 128) + r0) * K3 + cc * 8;
    const unsigned short* bS = Bu + ((size_t)(nb * 128) + r0) * K3 + cc * 8;
    const size_t rowskip = (size_t)64 * K3;
    const uint32_t dOff = (uint32_t)(r0 * ROWB + cc * 16);

    float acc[4][4][4];
    #pragma unroll
    for (int i = 0; i < 4; i++)
        #pragma unroll
        for (int j = 0; j < 4; j++)
            #pragma unroll
            for (int r = 0; r < 4; r++) acc[i][j][r] = 0.f;

    const int nc = K3 / BK;

    auto LOAD = [&](int s, int c) {
        const uint32_t d = sb + s * STG_B + dOff;
        const unsigned short* a = aS + (size_t)c * BK;
        const unsigned short* b = bS + (size_t)c * BK;
        cp16(d,                    a);
        cp16(d + 64 * ROWB,        a + rowskip);
        cp16(d + B_OFF,            b);
        cp16(d + B_OFF + 64*ROWB,  b + rowskip);
    };

    LOAD(0, 0); CP_COMMIT();
    LOAD(1, 1); CP_COMMIT();

    const uint32_t aRow = (uint32_t)(wm * 64 + (lane & 15));
    const uint32_t aK   = ((lane >> 4) & 1) * 16;
    const uint32_t bRow = (uint32_t)(wn * 32 + ((lane >> 4) & 1) * 8 + (lane & 7));
    const uint32_t bK   = ((lane >> 3) & 1) * 16;

    for (int c = 0; c < nc; c++) {
        if (c + 2 < nc) LOAD((c + 2) % NSTAGE, c + 2);
        CP_COMMIT();
        CP_WAIT2();
        __syncthreads();
        const uint32_t base = sb + (c % NSTAGE) * STG_B;
        #pragma unroll
        for (int ks = 0; ks < 2; ks++) {
            uint32_t af[4][4], bf[2][4];
            #pragma unroll
            for (int mt = 0; mt < 4; mt++) {
                const uint32_t ad = base + (aRow + mt * 16) * ROWB + ks * 32 + aK;
                LDSM4(af[mt][0], af[mt][1], af[mt][2], af[mt][3], ad);
            }
            #pragma unroll
            for (int j = 0; j < 2; j++) {
                const uint32_t bd = base + B_OFF + (bRow + j * 16) * ROWB + ks * 32 + bK;
                LDSM4(bf[j][0], bf[j][1], bf[j][2], bf[j][3], bd);
            }
            #pragma unroll
            for (int mt = 0; mt < 4; mt++)
                #pragma unroll
                for (int nt = 0; nt < 4; nt++)
                    MMA16816(acc[mt][nt], af[mt],
                             bf[nt >> 1][(nt & 1) * 2], bf[nt >> 1][(nt & 1) * 2 + 1]);
        }
        __syncthreads();
    }

    // ---------------- epilogue (fused conversions) ----------------
    const int row0 = mb * 128 + wm * 64 + (lane >> 2);
    const int col0 = nb * 128 + wn * 32 + (lane & 3) * 2;
    #pragma unroll
    for (int mt = 0; mt < 4; mt++) {
        const int r1 = row0 + mt * 16;
        const int r2 = r1 + 8;
        #pragma unroll
        for (int nt = 0; nt < 4; nt++) {
            const int cn = col0 + nt * 8;
            const float bx = __ldg(bias + cn), by = __ldg(bias + cn + 1);
            float o10 = acc[mt][nt][0] + bx, o11 = acc[mt][nt][1] + by;
            float o20 = acc[mt][nt][2] + bx, o21 = acc[mt][nt][3] + by;
            if (mode == 0) {
                *(float2*)(Cf + (size_t)r1 * N + cn) = make_float2(o10, o11);
                *(float2*)(Cf + (size_t)r2 * N + cn) = make_float2(o20, o21);
            } else if (mode == 4) {
                unsigned short h0, l0, h1, l1;
                bfsplit(o10, h0, l0); bfsplit(o11, h1, l1);
                uint32_t hp = (uint32_t)h0 | ((uint32_t)h1 << 16);
                uint32_t lp = (uint32_t)l0 | ((uint32_t)l1 << 16);
                unsigned short* p = Cs + (size_t)r1 * (2 * N) + cn;
                *(uint32_t*)p = hp; *(uint32_t*)(p + N) = lp;
                bfsplit(o20, h0, l0); bfsplit(o21, h1, l1);
                hp = (uint32_t)h0 | ((uint32_t)h1 << 16);
                lp = (uint32_t)l0 | ((uint32_t)l1 << 16);
                p = Cs + (size_t)r2 * (2 * N) + cn;
                *(uint32_t*)p = hp; *(uint32_t*)(p + N) = lp;
            } else {
                if (mode == 1) {
                    o10 = fmaxf(o10, 0.f); o11 = fmaxf(o11, 0.f);
                    o20 = fmaxf(o20, 0.f); o21 = fmaxf(o21, 0.f);
                } else if (mode == 2) {
                    o10 *= 0.125f; o11 *= 0.125f; o20 *= 0.125f; o21 *= 0.125f;
                }
                unsigned short h0, l0, h1, l1;
                bfsplit(o10, h0, l0); bfsplit(o11, h1, l1);
                uint32_t hp = (uint32_t)h0 | ((uint32_t)h1 << 16);
                uint32_t lp = (uint32_t)l0 | ((uint32_t)l1 << 16);
                unsigned short* p = Cs + (size_t)r1 * (3 * N) + cn;
                if (mode == 3) { *(uint32_t*)p = hp; *(uint32_t*)(p + N) = lp; *(uint32_t*)(p + 2 * N) = hp; }
                else           { *(uint32_t*)p = hp; *(uint32_t*)(p + N) = hp; *(uint32_t*)(p + 2 * N) = lp; }
                bfsplit(o20, h0, l0); bfsplit(o21, h1, l1);
                hp = (uint32_t)h0 | ((uint32_t)h1 << 16);
                lp = (uint32_t)l0 | ((uint32_t)l1 << 16);
                p = Cs + (size_t)r2 * (3 * N) + cn;
                if (mode == 3) { *(uint32_t*)p = hp; *(uint32_t*)(p + N) = lp; *(uint32_t*)(p + 2 * N) = hp; }
                else           { *(uint32_t*)p = hp; *(uint32_t*)(p + N) = hp; *(uint32_t*)(p + 2 * N) = lp; }
            }
        }
    }
}

// ---------------------------------------------------------------------------
// Tensor-core flash attention. Inputs PRE-SPLIT bf16:
//   Qg [m][3D]: (hi,hi,lo) scaled 1/8; Kg [m][3D]: (hi,lo,hi); Vg [m][2D]: hi|lo
// Epilogue writes split A'' (hi,hi,lo) into g_aatt.
// ---------------------------------------------------------------------------
#define AQROWB 400
#define AVROWB 144
#define ATT2_SMEM (2*64*AQROWB + 2*64*AVROWB)   // 69632

__global__ __launch_bounds__(128) void attn_tc_kernel(
    const unsigned short* __restrict__ Qg, const unsigned short* __restrict__ Kg,
    const unsigned short* __restrict__ Vg, unsigned short* __restrict__ Aout)
{
    extern __shared__ char sm8[];
    char* Qs = sm8;
    char* Ks = Qs + 64 * AQROWB;
    char* Vh = Ks + 64 * AQROWB;
    char* Vl = Vh + 64 * AVROWB;
    const uint32_t qsb = smem_u32(Qs), ksb = smem_u32(Ks);
    const uint32_t vhb = smem_u32(Vh), vlb = smem_u32(Vl);

    const int tid = threadIdx.x, wid = tid >> 5, lane = tid & 31;
    const int q0 = blockIdx.x * 64;
    const int b = blockIdx.y >> 4, h = blockIdx.y & 15;
    const size_t bS = (size_t)b * SS;

    // ---- load Q tile ----
    {
        const int r = tid >> 1, half = tid & 1;
        const unsigned short* src = Qg + (bS + q0 + r) * (size_t)(3 * DD) + h * 64;
        char* drow = Qs + r * AQROWB;
        #pragma unroll
        for (int ch = 0; ch < 12; ch++) {
            const int c = half * 12 + ch;
            const int seg = c >> 3, off = c & 7;
            *(uint4*)(drow + (seg * 64 + off * 8) * 2) =
                *(const uint4*)(src + seg * DD + off * 8);
        }
    }
    __syncthreads();

    uint32_t qf[12][4];
    {
        const uint32_t ab = qsb + (wid * 16 + (lane & 15)) * AQROWB + ((lane >> 4) & 1) * 16;
        #pragma unroll
        for (int ks = 0; ks < 12; ks++)
            LDSM4(qf[ks][0], qf[ks][1], qf[ks][2], qf[ks][3], ab + ks * 32);
    }

    const uint32_t bRow = ((lane >> 4) & 1) * 8 + (lane & 7);
    const uint32_t bK   = ((lane >> 3) & 1) * 16;
    const uint32_t vLn  = (lane & 15);
    const uint32_t vCo  = ((lane >> 4) & 1) * 16;

    float O[8][4];
    #pragma unroll
    for (int j = 0; j < 8; j++)
        #pragma unroll
        for (int r = 0; r < 4; r++) O[j][r] = 0.f;
    float m0 = -1e30f, m1 = -1e30f, l0 = 0.f, l1 = 0.f;

    const int r0l = wid * 16 + (lane >> 2);
    const int r1l = r0l + 8;

    for (int kt = 0; kt <= blockIdx.x; kt++) {
        const int k0 = kt * 64;
        __syncthreads();
        {
            const int r = tid >> 1, half = tid & 1;
            const unsigned short* ksrc = Kg + (bS + k0 + r) * (size_t)(3 * DD) + h * 64;
            char* krow = Ks + r * AQROWB;
            #pragma unroll
            for (int ch = 0; ch < 12; ch++) {
                const int c = half * 12 + ch;
                const int seg = c >> 3, off = c & 7;
                *(uint4*)(krow + (seg * 64 + off * 8) * 2) =
                    *(const uint4*)(ksrc + seg * DD + off * 8);
            }
            const unsigned short* vsrc = Vg + (bS + k0 + r) * (size_t)(2 * DD)
                                            + half * DD + h * 64;
            char* vrow = (half ? Vl : Vh) + r * AVROWB;
            #pragma unroll
            for (int off = 0; off < 8; off++)
                *(uint4*)(vrow + off * 16) = *(const uint4*)(vsrc + off * 8);
        }
        __syncthreads();

        float s[8][4];
        #pragma unroll
        for (int j = 0; j < 8; j++)
            #pragma unroll
            for (int r = 0; r < 4; r++) s[j][r] = 0.f;
        #pragma unroll
        for (int ks = 0; ks < 12; ks++) {
            #pragma unroll
            for (int j16 = 0; j16 < 4; j16++) {
                uint32_t kf0, kf1, kf2, kf3;
                LDSM4(kf0, kf1, kf2, kf3,
                      ksb + (j16 * 16 + bRow) * AQROWB + ks * 32 + bK);
                MMA16816(s[2 * j16],     qf[ks], kf0, kf1);
                MMA16816(s[2 * j16 + 1], qf[ks], kf2, kf3);
            }
        }

        if (kt == (int)blockIdx.x) {
            #pragma unroll
            for (int j = 0; j < 8; j++) {
                const int c = j * 8 + 2 * (lane & 3);
                if (c     > r0l) s[j][0] = -1e30f;
                if (c + 1 > r0l) s[j][1] = -1e30f;
                if (c     > r1l) s[j][2] = -1e30f;
                if (c + 1 > r1l) s[j][3] = -1e30f;
            }
        }

        float mx0 = -1e30f, mx1 = -1e30f;
        #pragma unroll
        for (int j = 0; j < 8; j++) {
            mx0 = fmaxf(mx0, fmaxf(s[j][0], s[j][1]));
            mx1 = fmaxf(mx1, fmaxf(s[j][2], s[j][3]));
        }
        mx0 = fmaxf(mx0, __shfl_xor_sync(0xffffffffu, mx0, 1));
        mx0 = fmaxf(mx0, __shfl_xor_sync(0xffffffffu, mx0, 2));
        mx1 = fmaxf(mx1, __shfl_xor_sync(0xffffffffu, mx1, 1));
        mx1 = fmaxf(mx1, __shfl_xor_sync(0xffffffffu, mx1, 2));
        const float mn0 = fmaxf(m0, mx0), mn1 = fmaxf(m1, mx1);
        const float cr0 = __expf(m0 - mn0), cr1 = __expf(m1 - mn1);
        m0 = mn0; m1 = mn1;
        float sum0 = 0.f, sum1 = 0.f;
        #pragma unroll
        for (int j = 0; j < 8; j++) {
            s[j][0] = __expf(s[j][0] - mn0);
            s[j][1] = __expf(s[j][1] - mn0);
            s[j][2] = __expf(s[j][2] - mn1);
            s[j][3] = __expf(s[j][3] - mn1);
            sum0 += s[j][0] + s[j][1];
            sum1 += s[j][2] + s[j][3];
        }
        sum0 += __shfl_xor_sync(0xffffffffu, sum0, 1);
        sum0 += __shfl_xor_sync(0xffffffffu, sum0, 2);
        sum1 += __shfl_xor_sync(0xffffffffu, sum1, 1);
        sum1 += __shfl_xor_sync(0xffffffffu, sum1, 2);
        l0 = l0 * cr0 + sum0;
        l1 = l1 * cr1 + sum1;
        #pragma unroll
        for (int j = 0; j < 8; j++) {
            O[j][0] *= cr0; O[j][1] *= cr0;
            O[j][2] *= cr1; O[j][3] *= cr1;
        }

        uint32_t phi[4][4], plo[4][4];
        #pragma unroll
        for (int ks2 = 0; ks2 < 4; ks2++) {
            const int j0 = 2 * ks2, j1 = j0 + 1;
            unsigned short h00, l00, h01, l01, h10, l10, h11, l11;
            bfsplit(s[j0][0], h00, l00); bfsplit(s[j0][1], h01, l01);
            phi[ks2][0] = (uint32_t)h00 | ((uint32_t)h01 << 16);
            plo[ks2][0] = (uint32_t)l00 | ((uint32_t)l01 << 16);
            bfsplit(s[j0][2], h10, l10); bfsplit(s[j0][3], h11, l11);
            phi[ks2][1] = (uint32_t)h10 | ((uint32_t)h11 << 16);
            plo[ks2][1] = (uint32_t)l10 | ((uint32_t)l11 << 16);
            bfsplit(s[j1][0], h00, l00); bfsplit(s[j1][1], h01, l01);
            phi[ks2][2] = (uint32_t)h00 | ((uint32_t)h01 << 16);
            plo[ks2][2] = (uint32_t)l00 | ((uint32_t)l01 << 16);
            bfsplit(s[j1][2], h10, l10); bfsplit(s[j1][3], h11, l11);
            phi[ks2][3] = (uint32_t)h10 | ((uint32_t)h11 << 16);
            plo[ks2][3] = (uint32_t)l10 | ((uint32_t)l11 << 16);
        }

        #pragma unroll
        for (int ks2 = 0; ks2 < 4; ks2++) {
            const uint32_t rowOff = (ks2 * 16 + vLn);
            #pragma unroll
            for (int dj = 0; dj < 4; dj++) {
                uint32_t vh0, vh1, vh2, vh3, vl0, vl1, vl2, vl3;
                LDSM4T(vh0, vh1, vh2, vh3, vhb + rowOff * AVROWB + dj * 32 + vCo);
                LDSM4T(vl0, vl1, vl2, vl3, vlb + rowOff * AVROWB + dj * 32 + vCo);
                MMA16816(O[2 * dj],     phi[ks2], vh0, vh1);
                MMA16816(O[2 * dj + 1], phi[ks2], vh2, vh3);
                MMA16816(O[2 * dj],     phi[ks2], vl0, vl1);
                MMA16816(O[2 * dj + 1], phi[ks2], vl2, vl3);
                MMA16816(O[2 * dj],     plo[ks2], vh0, vh1);
                MMA16816(O[2 * dj + 1], plo[ks2], vh2, vh3);
            }
        }
    }

    const float inv0 = 1.f / l0, inv1 = 1.f / l1;
    const size_t m0g = bS + (q0 + r0l);
    const size_t m1g = m0g + 8;
    const int cb = h * 64 + 2 * (lane & 3);
    unsigned short* out0 = Aout + m0g * (size_t)(3 * DD) + cb;
    unsigned short* out1 = Aout + m1g * (size_t)(3 * DD) + cb;
    #pragma unroll
    for (int j = 0; j < 8; j++) {
        const int d = j * 8;
        unsigned short ha, la, hb2, lb2;
        bfsplit(O[j][0] * inv0, ha, la);
        bfsplit(O[j][1] * inv0, hb2, lb2);
        uint32_t hp = (uint32_t)ha | ((uint32_t)hb2 << 16);
        uint32_t lp = (uint32_t)la | ((uint32_t)lb2 << 16);
        *(uint32_t*)(out0 + d)            = hp;
        *(uint32_t*)(out0 + DD + d)       = hp;
        *(uint32_t*)(out0 + 2 * DD + d)   = lp;
        bfsplit(O[j][2] * inv1, ha, la);
        bfsplit(O[j][3] * inv1, hb2, lb2);
        hp = (uint32_t)ha | ((uint32_t)hb2 << 16);
        lp = (uint32_t)la | ((uint32_t)lb2 << 16);
        *(uint32_t*)(out1 + d)            = hp;
        *(uint32_t*)(out1 + DD + d)       = hp;
        *(uint32_t*)(out1 + 2 * DD + d)   = lp;
    }
}

// ---------------------------------------------------------------------------
// out = LayerNorm(x + y) * gamma + beta; optional fused split (hi,hi,lo)
// ---------------------------------------------------------------------------
__device__ __forceinline__ float block_sum(float v, float* sh)
{
    const int lane = threadIdx.x & 31, w = threadIdx.x >> 5;
    #pragma unroll
    for (int o = 16; o; o >>= 1) v += __shfl_xor_sync(0xffffffffu, v, o);
    if (lane == 0) sh[w] = v;
    __syncthreads();
    float r = (lane < 8) ? sh[lane] : 0.f;
    #pragma unroll
    for (int o = 4; o; o >>= 1) r += __shfl_xor_sync(0xffffffffu, r, o);
    if (threadIdx.x == 0) sh[0] = r;
    __syncthreads();
    r = sh[0];
    __syncthreads();
    return r;
}

__global__ __launch_bounds__(256) void add_ln_kernel(
    const float* __restrict__ X, const float* __restrict__ Y,
    const float* __restrict__ g, const float* __restrict__ bta,
    float* __restrict__ out, unsigned short* __restrict__ As)
{
    __shared__ float sh[32];
    const size_t row = blockIdx.x;
    const int t = threadIdx.x;
    const float4 xv = ((const float4*)(X + row * DD))[t];
    const float4 yv = ((const float4*)(Y + row * DD))[t];
    float v0 = xv.x + yv.x, v1 = xv.y + yv.y, v2 = xv.z + yv.z, v3 = xv.w + yv.w;
    const float mean = block_sum(v0 + v1 + v2 + v3, sh) * (1.f / DD);
    const float d0 = v0 - mean, d1 = v1 - mean, d2 = v2 - mean, d3 = v3 - mean;
    const float var = block_sum(d0*d0 + d1*d1 + d2*d2 + d3*d3, sh) * (1.f / DD);
    const float inv = rsqrtf(var + 1e-5f);
    const float4 gv = ((const float4*)g)[t];
    const float4 bv = ((const float4*)bta)[t];
    float4 o;
    o.x = d0 * inv * gv.x + bv.x;
    o.y = d1 * inv * gv.y + bv.y;
    o.z = d2 * inv * gv.z + bv.z;
    o.w = d3 * inv * gv.w + bv.w;
    ((float4*)(out + row * DD))[t] = o;
    if (As) {
        unsigned short h0, l0, h1, l1, h2, l2, h3, l3;
        bfsplit(o.x, h0, l0); bfsplit(o.y, h1, l1);
        bfsplit(o.z, h2, l2); bfsplit(o.w, h3, l3);
        uint2 hp = make_uint2((uint32_t)h0 | ((uint32_t)h1 << 16),
                              (uint32_t)h2 | ((uint32_t)h3 << 16));
        uint2 lp = make_uint2((uint32_t)l0 | ((uint32_t)l1 << 16),
                              (uint32_t)l2 | ((uint32_t)l3 << 16));
        unsigned short* p = As + row * (size_t)(3 * DD) + t * 4;
        *(uint2*)p            = hp;
        *(uint2*)(p + DD)     = hp;
        *(uint2*)(p + 2 * DD) = lp;
    }
}

// ---------------------------------------------------------------------------
// Launcher
// ---------------------------------------------------------------------------
extern "C" void kernel_launch(void* const* d_in, const int* in_sizes, int n_in,
                              void* d_out, int out_size)
{
    (void)in_sizes; (void)n_in; (void)out_size;
    const float* x  = (const float*)d_in[0];
    const float* Wq = (const float*)d_in[2];
    const float* bq = (const float*)d_in[3];
    const float* Wk = (const float*)d_in[4];
    const float* bk = (const float*)d_in[5];
    const float* Wv = (const float*)d_in[6];
    const float* bv = (const float*)d_in[7];
    const float* Wo = (const float*)d_in[8];
    const float* bo = (const float*)d_in[9];
    const float* g1 = (const float*)d_in[10];
    const float* b1 = (const float*)d_in[11];
    const float* W1 = (const float*)d_in[12];
    const float* c1 = (const float*)d_in[13];
    const float* W2 = (const float*)d_in[14];
    const float* c2 = (const float*)d_in[15];
    const float* g2 = (const float*)d_in[16];
    const float* b2 = (const float*)d_in[17];
    float* out = (float*)d_out;

    float *proj, *x1, *ff2;
    cudaGetSymbolAddress((void**)&proj, g_proj);
    cudaGetSymbolAddress((void**)&x1,   g_x1);
    cudaGetSymbolAddress((void**)&ff2,  g_ff2);

    unsigned short *ax, *qs, *ks, *vs, *aatt, *ax1, *aff1;
    unsigned short *wq2, *wk2, *wv2, *wo2, *w12, *w22;
    cudaGetSymbolAddress((void**)&ax,   g_ax);
    cudaGetSymbolAddress((void**)&qs,   g_qs);
    cudaGetSymbolAddress((void**)&ks,   g_ks);
    cudaGetSymbolAddress((void**)&vs,   g_vs);
    cudaGetSymbolAddress((void**)&aatt, g_aatt);
    cudaGetSymbolAddress((void**)&ax1,  g_ax1);
    cudaGetSymbolAddress((void**)&aff1, g_aff1);
    cudaGetSymbolAddress((void**)&wq2,  g_wq);
    cudaGetSymbolAddress((void**)&wk2,  g_wk);
    cudaGetSymbolAddress((void**)&wv2,  g_wv);
    cudaGetSymbolAddress((void**)&wo2,  g_wo);
    cudaGetSymbolAddress((void**)&w12,  g_w1);
    cudaGetSymbolAddress((void**)&w22,  g_w2);

    cudaFuncSetAttribute(mma_gemm_kernel,
                         cudaFuncAttributeMaxDynamicSharedMemorySize, GEMM_SMEM);
    cudaFuncSetAttribute(attn_tc_kernel,
                         cudaFuncAttributeMaxDynamicSharedMemorySize, ATT2_SMEM);

    const dim3 blk(256);
    const dim3 wblk(32, 8);
    const dim3 gD(DD/128, MM/128);       // N=1024 GEMMs
    const dim3 gF(FF/128, MM/128);       // N=4096 GEMM

    convert_w_kernel<<<dim3(DD/32, DD/32), wblk>>>(Wq, wq2, DD, DD);
    convert_w_kernel<<<dim3(DD/32, DD/32), wblk>>>(Wk, wk2, DD, DD);
    convert_w_kernel<<<dim3(DD/32, DD/32), wblk>>>(Wv, wv2, DD, DD);
    convert_w_kernel<<<dim3(DD/32, DD/32), wblk>>>(Wo, wo2, DD, DD);
    convert_a_kernel<<<(int)(((size_t)MM*DD/4 + 255)/256), blk>>>(x, ax, DD);

    // QKV projections -> pre-split bf16 layouts
    mma_gemm_kernel<<<gD, blk, GEMM_SMEM>>>(ax, wq2, bq, nullptr, qs, DD, 3*DD, 2);
    mma_gemm_kernel<<<gD, blk, GEMM_SMEM>>>(ax, wk2, bk, nullptr, ks, DD, 3*DD, 3);
    mma_gemm_kernel<<<gD, blk, GEMM_SMEM>>>(ax, wv2, bv, nullptr, vs, DD, 3*DD, 4);

    // attention (pre-split inputs, writes split A'')
    attn_tc_kernel<<<dim3(SS/64, BB*HH), 128, ATT2_SMEM>>>(qs, ks, vs, aatt);

    // output projection + residual LN (fused split of x1)
    mma_gemm_kernel<<<gD, blk, GEMM_SMEM>>>(aatt, wo2, bo, proj, nullptr, DD, 3*DD, 0);
    add_ln_kernel<<<MM, blk>>>(x, proj, g1, b1, x1, ax1);

    // FFN
    convert_w_kernel<<<dim3(FF/32, DD/32), wblk>>>(W1, w12, DD, FF);
    mma_gemm_kernel<<<gF, blk, GEMM_SMEM>>>(ax1, w12, c1, nullptr, aff1, FF, 3*DD, 1);
    convert_w_kernel<<<dim3(DD/32, FF/32), wblk>>>(W2, w22, FF, DD);
    mma_gemm_kernel<<<gD, blk, GEMM_SMEM>>>(aff1, w22, c2, ff2, nullptr, DD, 3*FF, 0);
    add_ln_kernel<<<MM, blk>>>(x1, ff2, g2, b2, out, nullptr);
}

// round 8
// speedup vs baseline: 1.5289x; 1.5289x over previous
#include <cuda_runtime.h>
#include <cuda_bf16.h>
#include <cstdint>
#include <cstddef>

// Problem constants
#define BB 4
#define SS 2048
#define DD 1024
#define HH 16
#define DKK 64
#define FF 4096
#define MM (BB*SS)          // 8192 rows

// ---------------------------------------------------------------------------
// Scratch (no allocations allowed -> __device__ globals)
// ---------------------------------------------------------------------------
__device__ float g_proj[(size_t)MM*DD];
__device__ float g_x1  [(size_t)MM*DD];
__device__ float g_ff2 [(size_t)MM*DD];

// split bf16 buffers
__device__ unsigned short g_ax  [(size_t)MM*3*DD];   // x      (hi,hi,lo)
__device__ unsigned short g_qs  [(size_t)MM*3*DD];   // q*1/8  (hi,hi,lo)
__device__ unsigned short g_ks  [(size_t)MM*3*DD];   // k      (hi,lo,hi)
__device__ unsigned short g_vs  [(size_t)MM*2*DD];   // v      (hi | lo)
__device__ unsigned short g_aatt[(size_t)MM*3*DD];   // attn out (hi,hi,lo)
__device__ unsigned short g_ax1 [(size_t)MM*3*DD];   // x1     (hi,hi,lo)
__device__ unsigned short g_aff1[(size_t)MM*3*FF];   // relu(ff1) (hi,hi,lo)
__device__ unsigned short g_wq  [(size_t)DD*3*DD];
__device__ unsigned short g_wk  [(size_t)DD*3*DD];
__device__ unsigned short g_wv  [(size_t)DD*3*DD];
__device__ unsigned short g_wo  [(size_t)DD*3*DD];
__device__ unsigned short g_w1  [(size_t)FF*3*DD];   // [N=F, 3K=3*D]
__device__ unsigned short g_w2  [(size_t)DD*3*FF];   // [N=D, 3K=3*F]

// ---------------------------------------------------------------------------
// Helpers (family-portable PTX only: cp.async / ldmatrix / mma.sync)
// ---------------------------------------------------------------------------
__device__ __forceinline__ uint32_t smem_u32(const void* p) {
    uint32_t a;
    asm("{ .reg .u64 t; cvta.to.shared.u64 t, %1; cvt.u32.u64 %0, t; }"
        : "=r"(a) : "l"(p));
    return a;
}

__device__ __forceinline__ void cp16(uint32_t dst, const void* src) {
    asm volatile("cp.async.cg.shared.global [%0], [%1], 16;" :: "r"(dst), "l"(src));
}

#define CP_COMMIT() asm volatile("cp.async.commit_group;")
#define CP_WAIT2()  asm volatile("cp.async.wait_group 2;" ::: "memory")

#define LDSM4(r0, r1, r2, r3, addr) \
    asm volatile("ldmatrix.sync.aligned.m8n8.x4.shared.b16 {%0,%1,%2,%3}, [%4];" \
        : "=r"(r0), "=r"(r1), "=r"(r2), "=r"(r3) : "r"(addr))

#define LDSM4T(r0, r1, r2, r3, addr) \
    asm volatile("ldmatrix.sync.aligned.m8n8.x4.trans.shared.b16 {%0,%1,%2,%3}, [%4];" \
        : "=r"(r0), "=r"(r1), "=r"(r2), "=r"(r3) : "r"(addr))

#define MMA16816(d, a, b0v, b1v) \
    asm volatile("mma.sync.aligned.m16n8k16.row.col.f32.bf16.bf16.f32 " \
        "{%0,%1,%2,%3}, {%4,%5,%6,%7}, {%8,%9}, {%0,%1,%2,%3};" \
        : "+f"((d)[0]), "+f"((d)[1]), "+f"((d)[2]), "+f"((d)[3]) \
        : "r"((a)[0]), "r"((a)[1]), "r"((a)[2]), "r"((a)[3]), "r"(b0v), "r"(b1v))

__device__ __forceinline__ unsigned short f2bf_bits(float f) {
    __nv_bfloat16 h = __float2bfloat16(f);
    return *reinterpret_cast<unsigned short*>(&h);
}
__device__ __forceinline__ void bfsplit(float x, unsigned short& h, unsigned short& l) {
    h = f2bf_bits(x);
    __nv_bfloat16 hb = *reinterpret_cast<__nv_bfloat16*>(&h);
    l = f2bf_bits(x - __bfloat162float(hb));
}

// ---------------------------------------------------------------------------
// fp32 -> (hi,hi,lo) bf16 K-expansion for activations. A''[m, 3K].
// ---------------------------------------------------------------------------
__global__ __launch_bounds__(256) void convert_a_kernel(
    const float* __restrict__ X, unsigned short* __restrict__ A, int K)
{
    size_t idx = (size_t)blockIdx.x * blockDim.x + threadIdx.x;
    size_t total = (size_t)MM * K / 4;
    if (idx >= total) return;
    size_t e = idx * 4;
    size_t m = e / K;
    int k = (int)(e % K);
    float4 v = *(const float4*)(X + e);
    unsigned short h0, h1, h2, h3, l0, l1, l2, l3;
    bfsplit(v.x, h0, l0); bfsplit(v.y, h1, l1);
    bfsplit(v.z, h2, l2); bfsplit(v.w, h3, l3);
    uint2 hp = make_uint2((uint32_t)h0 | ((uint32_t)h1 << 16),
                          (uint32_t)h2 | ((uint32_t)h3 << 16));
    uint2 lp = make_uint2((uint32_t)l0 | ((uint32_t)l1 << 16),
                          (uint32_t)l2 | ((uint32_t)l3 << 16));
    size_t ob = m * (size_t)(3 * K);
    *(uint2*)(A + ob + k)         = hp;
    *(uint2*)(A + ob + K + k)     = hp;
    *(uint2*)(A + ob + 2 * K + k) = lp;
}

// ---------------------------------------------------------------------------
// W[K,N] fp32 -> B''[N, 3K] bf16 with (hi, lo, hi) layout (transposed).
// ---------------------------------------------------------------------------
__global__ __launch_bounds__(256) void convert_w_kernel(
    const float* __restrict__ W, unsigned short* __restrict__ Bm, int K, int N)
{
    __shared__ float tile[32][33];
    const int n0 = blockIdx.x * 32;
    const int k0 = blockIdx.y * 32;
    for (int i = threadIdx.y; i < 32; i += 8)
        tile[i][threadIdx.x] = W[(size_t)(k0 + i) * N + n0 + threadIdx.x];
    __syncthreads();
    for (int i = threadIdx.y; i < 32; i += 8) {
        const int n = n0 + i;
        const int k = k0 + threadIdx.x;
        unsigned short h, l;
        bfsplit(tile[threadIdx.x][i], h, l);
        size_t ob = (size_t)n * (3 * K);
        Bm[ob + k]         = h;
        Bm[ob + K + k]     = l;
        Bm[ob + 2 * K + k] = h;
    }
}

// ---------------------------------------------------------------------------
// mma.sync bf16 GEMM: BM=BN=128, BK=32, 3-stage cp.async, 256 threads
// (8 warps 2x4, warp tile 64x32). __launch_bounds__(256, 2) pins the
// register budget to <=128 so the mode epilogue cannot kill occupancy
// (spills, if any, land in the once-per-CTA epilogue).
// Epilogue modes:
//   0: fp32 C = acc + bias
//   1: relu -> split (hi,hi,lo) into Cs[m][3N]
//   2: (acc+bias)*0.125 -> split (hi,hi,lo)   [Q]
//   3: split (hi,lo,hi)                        [K]
//   4: split (hi | lo) into Cs[m][2N]          [V]
// ---------------------------------------------------------------------------
#define BK 32
#define NSTAGE 3
#define ROWB 80
#define B_OFF (128*ROWB)
#define STG_B (2*B_OFF)
#define GEMM_SMEM (NSTAGE*STG_B)    // 61440

__global__ __launch_bounds__(256, 2) void mma_gemm_kernel(
    const unsigned short* __restrict__ Au, const unsigned short* __restrict__ Bu,
    const float* __restrict__ bias, float* __restrict__ Cf,
    unsigned short* __restrict__ Cs, int N, int K3, int mode)
{
    extern __shared__ char smem[];
    const uint32_t sb = smem_u32(smem);
    const int tid = threadIdx.x;
    const int wid = tid >> 5, lane = tid & 31;
    const int wm = wid >> 2, wn = wid & 3;
    const int mb = blockIdx.y, nb = blockIdx.x;

    const int r0 = tid >> 2, cc = tid & 3;
    const unsigned short* aS = Au + ((size_t)(mb * 128) + r0) * K3 + cc * 8;
    const unsigned short* bS = Bu + ((size_t)(nb * 128) + r0) * K3 + cc * 8;
    const size_t rowskip = (size_t)64 * K3;
    const uint32_t dOff = (uint32_t)(r0 * ROWB + cc * 16);

    float acc[4][4][4];
    #pragma unroll
    for (int i = 0; i < 4; i++)
        #pragma unroll
        for (int j = 0; j < 4; j++)
            #pragma unroll
            for (int r = 0; r < 4; r++) acc[i][j][r] = 0.f;

    const int nc = K3 / BK;

    auto LOAD = [&](int s, int c) {
        const uint32_t d = sb + s * STG_B + dOff;
        const unsigned short* a = aS + (size_t)c * BK;
        const unsigned short* b = bS + (size_t)c * BK;
        cp16(d,                    a);
        cp16(d + 64 * ROWB,        a + rowskip);
        cp16(d + B_OFF,            b);
        cp16(d + B_OFF + 64*ROWB,  b + rowskip);
    };

    LOAD(0, 0); CP_COMMIT();
    LOAD(1, 1); CP_COMMIT();

    const uint32_t aRow = (uint32_t)(wm * 64 + (lane & 15));
    const uint32_t aK   = ((lane >> 4) & 1) * 16;
    const uint32_t bRow = (uint32_t)(wn * 32 + ((lane >> 4) & 1) * 8 + (lane & 7));
    const uint32_t bK   = ((lane >> 3) & 1) * 16;

    for (int c = 0; c < nc; c++) {
        if (c + 2 < nc) LOAD((c + 2) % NSTAGE, c + 2);
        CP_COMMIT();
        CP_WAIT2();
        __syncthreads();
        const uint32_t base = sb + (c % NSTAGE) * STG_B;
        #pragma unroll
        for (int ks = 0; ks < 2; ks++) {
            uint32_t af[4][4], bf[2][4];
            #pragma unroll
            for (int mt = 0; mt < 4; mt++) {
                const uint32_t ad = base + (aRow + mt * 16) * ROWB + ks * 32 + aK;
                LDSM4(af[mt][0], af[mt][1], af[mt][2], af[mt][3], ad);
            }
            #pragma unroll
            for (int j = 0; j < 2; j++) {
                const uint32_t bd = base + B_OFF + (bRow + j * 16) * ROWB + ks * 32 + bK;
                LDSM4(bf[j][0], bf[j][1], bf[j][2], bf[j][3], bd);
            }
            #pragma unroll
            for (int mt = 0; mt < 4; mt++)
                #pragma unroll
                for (int nt = 0; nt < 4; nt++)
                    MMA16816(acc[mt][nt], af[mt],
                             bf[nt >> 1][(nt & 1) * 2], bf[nt >> 1][(nt & 1) * 2 + 1]);
        }
        __syncthreads();
    }

    // ---------------- epilogue (fused conversions) ----------------
    const int row0 = mb * 128 + wm * 64 + (lane >> 2);
    const int col0 = nb * 128 + wn * 32 + (lane & 3) * 2;
    #pragma unroll
    for (int mt = 0; mt < 4; mt++) {
        const int r1 = row0 + mt * 16;
        const int r2 = r1 + 8;
        #pragma unroll
        for (int nt = 0; nt < 4; nt++) {
            const int cn = col0 + nt * 8;
            const float bx = __ldg(bias + cn), by = __ldg(bias + cn + 1);
            float o10 = acc[mt][nt][0] + bx, o11 = acc[mt][nt][1] + by;
            float o20 = acc[mt][nt][2] + bx, o21 = acc[mt][nt][3] + by;
            if (mode == 0) {
                *(float2*)(Cf + (size_t)r1 * N + cn) = make_float2(o10, o11);
                *(float2*)(Cf + (size_t)r2 * N + cn) = make_float2(o20, o21);
            } else if (mode == 4) {
                unsigned short h0, l0, h1, l1;
                bfsplit(o10, h0, l0); bfsplit(o11, h1, l1);
                uint32_t hp = (uint32_t)h0 | ((uint32_t)h1 << 16);
                uint32_t lp = (uint32_t)l0 | ((uint32_t)l1 << 16);
                unsigned short* p = Cs + (size_t)r1 * (2 * N) + cn;
                *(uint32_t*)p = hp; *(uint32_t*)(p + N) = lp;
                bfsplit(o20, h0, l0); bfsplit(o21, h1, l1);
                hp = (uint32_t)h0 | ((uint32_t)h1 << 16);
                lp = (uint32_t)l0 | ((uint32_t)l1 << 16);
                p = Cs + (size_t)r2 * (2 * N) + cn;
                *(uint32_t*)p = hp; *(uint32_t*)(p + N) = lp;
            } else {
                if (mode == 1) {
                    o10 = fmaxf(o10, 0.f); o11 = fmaxf(o11, 0.f);
                    o20 = fmaxf(o20, 0.f); o21 = fmaxf(o21, 0.f);
                } else if (mode == 2) {
                    o10 *= 0.125f; o11 *= 0.125f; o20 *= 0.125f; o21 *= 0.125f;
                }
                unsigned short h0, l0, h1, l1;
                bfsplit(o10, h0, l0); bfsplit(o11, h1, l1);
                uint32_t hp = (uint32_t)h0 | ((uint32_t)h1 << 16);
                uint32_t lp = (uint32_t)l0 | ((uint32_t)l1 << 16);
                unsigned short* p = Cs + (size_t)r1 * (3 * N) + cn;
                if (mode == 3) { *(uint32_t*)p = hp; *(uint32_t*)(p + N) = lp; *(uint32_t*)(p + 2 * N) = hp; }
                else           { *(uint32_t*)p = hp; *(uint32_t*)(p + N) = hp; *(uint32_t*)(p + 2 * N) = lp; }
                bfsplit(o20, h0, l0); bfsplit(o21, h1, l1);
                hp = (uint32_t)h0 | ((uint32_t)h1 << 16);
                lp = (uint32_t)l0 | ((uint32_t)l1 << 16);
                p = Cs + (size_t)r2 * (3 * N) + cn;
                if (mode == 3) { *(uint32_t*)p = hp; *(uint32_t*)(p + N) = lp; *(uint32_t*)(p + 2 * N) = hp; }
                else           { *(uint32_t*)p = hp; *(uint32_t*)(p + N) = hp; *(uint32_t*)(p + 2 * N) = lp; }
            }
        }
    }
}

// ---------------------------------------------------------------------------
// Tensor-core flash attention. Inputs PRE-SPLIT bf16:
//   Qg [m][3D]: (hi,hi,lo) scaled 1/8; Kg [m][3D]: (hi,lo,hi); Vg [m][2D]: hi|lo
// Epilogue writes split A'' (hi,hi,lo) into g_aatt.
// ---------------------------------------------------------------------------
#define AQROWB 400
#define AVROWB 144
#define ATT2_SMEM (2*64*AQROWB + 2*64*AVROWB)   // 69632

__global__ __launch_bounds__(128) void attn_tc_kernel(
    const unsigned short* __restrict__ Qg, const unsigned short* __restrict__ Kg,
    const unsigned short* __restrict__ Vg, unsigned short* __restrict__ Aout)
{
    extern __shared__ char sm8[];
    char* Qs = sm8;
    char* Ks = Qs + 64 * AQROWB;
    char* Vh = Ks + 64 * AQROWB;
    char* Vl = Vh + 64 * AVROWB;
    const uint32_t qsb = smem_u32(Qs), ksb = smem_u32(Ks);
    const uint32_t vhb = smem_u32(Vh), vlb = smem_u32(Vl);

    const int tid = threadIdx.x, wid = tid >> 5, lane = tid & 31;
    const int q0 = blockIdx.x * 64;
    const int b = blockIdx.y >> 4, h = blockIdx.y & 15;
    const size_t bS = (size_t)b * SS;

    // ---- load Q tile ----
    {
        const int r = tid >> 1, half = tid & 1;
        const unsigned short* src = Qg + (bS + q0 + r) * (size_t)(3 * DD) + h * 64;
        char* drow = Qs + r * AQROWB;
        #pragma unroll
        for (int ch = 0; ch < 12; ch++) {
            const int c = half * 12 + ch;
            const int seg = c >> 3, off = c & 7;
            *(uint4*)(drow + (seg * 64 + off * 8) * 2) =
                *(const uint4*)(src + seg * DD + off * 8);
        }
    }
    __syncthreads();

    uint32_t qf[12][4];
    {
        const uint32_t ab = qsb + (wid * 16 + (lane & 15)) * AQROWB + ((lane >> 4) & 1) * 16;
        #pragma unroll
        for (int ks = 0; ks < 12; ks++)
            LDSM4(qf[ks][0], qf[ks][1], qf[ks][2], qf[ks][3], ab + ks * 32);
    }

    const uint32_t bRow = ((lane >> 4) & 1) * 8 + (lane & 7);
    const uint32_t bK   = ((lane >> 3) & 1) * 16;
    const uint32_t vLn  = (lane & 15);
    const uint32_t vCo  = ((lane >> 4) & 1) * 16;

    float O[8][4];
    #pragma unroll
    for (int j = 0; j < 8; j++)
        #pragma unroll
        for (int r = 0; r < 4; r++) O[j][r] = 0.f;
    float m0 = -1e30f, m1 = -1e30f, l0 = 0.f, l1 = 0.f;

    const int r0l = wid * 16 + (lane >> 2);
    const int r1l = r0l + 8;

    for (int kt = 0; kt <= blockIdx.x; kt++) {
        const int k0 = kt * 64;
        __syncthreads();
        {
            const int r = tid >> 1, half = tid & 1;
            const unsigned short* ksrc = Kg + (bS + k0 + r) * (size_t)(3 * DD) + h * 64;
            char* krow = Ks + r * AQROWB;
            #pragma unroll
            for (int ch = 0; ch < 12; ch++) {
                const int c = half * 12 + ch;
                const int seg = c >> 3, off = c & 7;
                *(uint4*)(krow + (seg * 64 + off * 8) * 2) =
                    *(const uint4*)(ksrc + seg * DD + off * 8);
            }
            const unsigned short* vsrc = Vg + (bS + k0 + r) * (size_t)(2 * DD)
                                            + half * DD + h * 64;
            char* vrow = (half ? Vl : Vh) + r * AVROWB;
            #pragma unroll
            for (int off = 0; off < 8; off++)
                *(uint4*)(vrow + off * 16) = *(const uint4*)(vsrc + off * 8);
        }
        __syncthreads();

        float s[8][4];
        #pragma unroll
        for (int j = 0; j < 8; j++)
            #pragma unroll
            for (int r = 0; r < 4; r++) s[j][r] = 0.f;
        #pragma unroll
        for (int ks = 0; ks < 12; ks++) {
            #pragma unroll
            for (int j16 = 0; j16 < 4; j16++) {
                uint32_t kf0, kf1, kf2, kf3;
                LDSM4(kf0, kf1, kf2, kf3,
                      ksb + (j16 * 16 + bRow) * AQROWB + ks * 32 + bK);
                MMA16816(s[2 * j16],     qf[ks], kf0, kf1);
                MMA16816(s[2 * j16 + 1], qf[ks], kf2, kf3);
            }
        }

        if (kt == (int)blockIdx.x) {
            #pragma unroll
            for (int j = 0; j < 8; j++) {
                const int c = j * 8 + 2 * (lane & 3);
                if (c     > r0l) s[j][0] = -1e30f;
                if (c + 1 > r0l) s[j][1] = -1e30f;
                if (c     > r1l) s[j][2] = -1e30f;
                if (c + 1 > r1l) s[j][3] = -1e30f;
            }
        }

        float mx0 = -1e30f, mx1 = -1e30f;
        #pragma unroll
        for (int j = 0; j < 8; j++) {
            mx0 = fmaxf(mx0, fmaxf(s[j][0], s[j][1]));
            mx1 = fmaxf(mx1, fmaxf(s[j][2], s[j][3]));
        }
        mx0 = fmaxf(mx0, __shfl_xor_sync(0xffffffffu, mx0, 1));
        mx0 = fmaxf(mx0, __shfl_xor_sync(0xffffffffu, mx0, 2));
        mx1 = fmaxf(mx1, __shfl_xor_sync(0xffffffffu, mx1, 1));
        mx1 = fmaxf(mx1, __shfl_xor_sync(0xffffffffu, mx1, 2));
        const float mn0 = fmaxf(m0, mx0), mn1 = fmaxf(m1, mx1);
        const float cr0 = __expf(m0 - mn0), cr1 = __expf(m1 - mn1);
        m0 = mn0; m1 = mn1;
        float sum0 = 0.f, sum1 = 0.f;
        #pragma unroll
        for (int j = 0; j < 8; j++) {
            s[j][0] = __expf(s[j][0] - mn0);
            s[j][1] = __expf(s[j][1] - mn0);
            s[j][2] = __expf(s[j][2] - mn1);
            s[j][3] = __expf(s[j][3] - mn1);
            sum0 += s[j][0] + s[j][1];
            sum1 += s[j][2] + s[j][3];
        }
        sum0 += __shfl_xor_sync(0xffffffffu, sum0, 1);
        sum0 += __shfl_xor_sync(0xffffffffu, sum0, 2);
        sum1 += __shfl_xor_sync(0xffffffffu, sum1, 1);
        sum1 += __shfl_xor_sync(0xffffffffu, sum1, 2);
        l0 = l0 * cr0 + sum0;
        l1 = l1 * cr1 + sum1;
        #pragma unroll
        for (int j = 0; j < 8; j++) {
            O[j][0] *= cr0; O[j][1] *= cr0;
            O[j][2] *= cr1; O[j][3] *= cr1;
        }

        uint32_t phi[4][4], plo[4][4];
        #pragma unroll
        for (int ks2 = 0; ks2 < 4; ks2++) {
            const int j0 = 2 * ks2, j1 = j0 + 1;
            unsigned short h00, l00, h01, l01, h10, l10, h11, l11;
            bfsplit(s[j0][0], h00, l00); bfsplit(s[j0][1], h01, l01);
            phi[ks2][0] = (uint32_t)h00 | ((uint32_t)h01 << 16);
            plo[ks2][0] = (uint32_t)l00 | ((uint32_t)l01 << 16);
            bfsplit(s[j0][2], h10, l10); bfsplit(s[j0][3], h11, l11);
            phi[ks2][1] = (uint32_t)h10 | ((uint32_t)h11 << 16);
            plo[ks2][1] = (uint32_t)l10 | ((uint32_t)l11 << 16);
            bfsplit(s[j1][0], h00, l00); bfsplit(s[j1][1], h01, l01);
            phi[ks2][2] = (uint32_t)h00 | ((uint32_t)h01 << 16);
            plo[ks2][2] = (uint32_t)l00 | ((uint32_t)l01 << 16);
            bfsplit(s[j1][2], h10, l10); bfsplit(s[j1][3], h11, l11);
            phi[ks2][3] = (uint32_t)h10 | ((uint32_t)h11 << 16);
            plo[ks2][3] = (uint32_t)l10 | ((uint32_t)l11 << 16);
        }

        #pragma unroll
        for (int ks2 = 0; ks2 < 4; ks2++) {
            const uint32_t rowOff = (ks2 * 16 + vLn);
            #pragma unroll
            for (int dj = 0; dj < 4; dj++) {
                uint32_t vh0, vh1, vh2, vh3, vl0, vl1, vl2, vl3;
                LDSM4T(vh0, vh1, vh2, vh3, vhb + rowOff * AVROWB + dj * 32 + vCo);
                LDSM4T(vl0, vl1, vl2, vl3, vlb + rowOff * AVROWB + dj * 32 + vCo);
                MMA16816(O[2 * dj],     phi[ks2], vh0, vh1);
                MMA16816(O[2 * dj + 1], phi[ks2], vh2, vh3);
                MMA16816(O[2 * dj],     phi[ks2], vl0, vl1);
                MMA16816(O[2 * dj + 1], phi[ks2], vl2, vl3);
                MMA16816(O[2 * dj],     plo[ks2], vh0, vh1);
                MMA16816(O[2 * dj + 1], plo[ks2], vh2, vh3);
            }
        }
    }

    const float inv0 = 1.f / l0, inv1 = 1.f / l1;
    const size_t m0g = bS + (q0 + r0l);
    const size_t m1g = m0g + 8;
    const int cb = h * 64 + 2 * (lane & 3);
    unsigned short* out0 = Aout + m0g * (size_t)(3 * DD) + cb;
    unsigned short* out1 = Aout + m1g * (size_t)(3 * DD) + cb;
    #pragma unroll
    for (int j = 0; j < 8; j++) {
        const int d = j * 8;
        unsigned short ha, la, hb2, lb2;
        bfsplit(O[j][0] * inv0, ha, la);
        bfsplit(O[j][1] * inv0, hb2, lb2);
        uint32_t hp = (uint32_t)ha | ((uint32_t)hb2 << 16);
        uint32_t lp = (uint32_t)la | ((uint32_t)lb2 << 16);
        *(uint32_t*)(out0 + d)            = hp;
        *(uint32_t*)(out0 + DD + d)       = hp;
        *(uint32_t*)(out0 + 2 * DD + d)   = lp;
        bfsplit(O[j][2] * inv1, ha, la);
        bfsplit(O[j][3] * inv1, hb2, lb2);
        hp = (uint32_t)ha | ((uint32_t)hb2 << 16);
        lp = (uint32_t)la | ((uint32_t)lb2 << 16);
        *(uint32_t*)(out1 + d)            = hp;
        *(uint32_t*)(out1 + DD + d)       = hp;
        *(uint32_t*)(out1 + 2 * DD + d)   = lp;
    }
}

// ---------------------------------------------------------------------------
// out = LayerNorm(x + y) * gamma + beta; optional fused split (hi,hi,lo)
// ---------------------------------------------------------------------------
__device__ __forceinline__ float block_sum(float v, float* sh)
{
    const int lane = threadIdx.x & 31, w = threadIdx.x >> 5;
    #pragma unroll
    for (int o = 16; o; o >>= 1) v += __shfl_xor_sync(0xffffffffu, v, o);
    if (lane == 0) sh[w] = v;
    __syncthreads();
    float r = (lane < 8) ? sh[lane] : 0.f;
    #pragma unroll
    for (int o = 4; o; o >>= 1) r += __shfl_xor_sync(0xffffffffu, r, o);
    if (threadIdx.x == 0) sh[0] = r;
    __syncthreads();
    r = sh[0];
    __syncthreads();
    return r;
}

__global__ __launch_bounds__(256) void add_ln_kernel(
    const float* __restrict__ X, const float* __restrict__ Y,
    const float* __restrict__ g, const float* __restrict__ bta,
    float* __restrict__ out, unsigned short* __restrict__ As)
{
    __shared__ float sh[32];
    const size_t row = blockIdx.x;
    const int t = threadIdx.x;
    const float4 xv = ((const float4*)(X + row * DD))[t];
    const float4 yv = ((const float4*)(Y + row * DD))[t];
    float v0 = xv.x + yv.x, v1 = xv.y + yv.y, v2 = xv.z + yv.z, v3 = xv.w + yv.w;
    const float mean = block_sum(v0 + v1 + v2 + v3, sh) * (1.f / DD);
    const float d0 = v0 - mean, d1 = v1 - mean, d2 = v2 - mean, d3 = v3 - mean;
    const float var = block_sum(d0*d0 + d1*d1 + d2*d2 + d3*d3, sh) * (1.f / DD);
    const float inv = rsqrtf(var + 1e-5f);
    const float4 gv = ((const float4*)g)[t];
    const float4 bv = ((const float4*)bta)[t];
    float4 o;
    o.x = d0 * inv * gv.x + bv.x;
    o.y = d1 * inv * gv.y + bv.y;
    o.z = d2 * inv * gv.z + bv.z;
    o.w = d3 * inv * gv.w + bv.w;
    ((float4*)(out + row * DD))[t] = o;
    if (As) {
        unsigned short h0, l0, h1, l1, h2, l2, h3, l3;
        bfsplit(o.x, h0, l0); bfsplit(o.y, h1, l1);
        bfsplit(o.z, h2, l2); bfsplit(o.w, h3, l3);
        uint2 hp = make_uint2((uint32_t)h0 | ((uint32_t)h1 << 16),
                              (uint32_t)h2 | ((uint32_t)h3 << 16));
        uint2 lp = make_uint2((uint32_t)l0 | ((uint32_t)l1 << 16),
                              (uint32_t)l2 | ((uint32_t)l3 << 16));
        unsigned short* p = As + row * (size_t)(3 * DD) + t * 4;
        *(uint2*)p            = hp;
        *(uint2*)(p + DD)     = hp;
        *(uint2*)(p + 2 * DD) = lp;
    }
}

// ---------------------------------------------------------------------------
// Launcher
// ---------------------------------------------------------------------------
extern "C" void kernel_launch(void* const* d_in, const int* in_sizes, int n_in,
                              void* d_out, int out_size)
{
    (void)in_sizes; (void)n_in; (void)out_size;
    const float* x  = (const float*)d_in[0];
    const float* Wq = (const float*)d_in[2];
    const float* bq = (const float*)d_in[3];
    const float* Wk = (const float*)d_in[4];
    const float* bk = (const float*)d_in[5];
    const float* Wv = (const float*)d_in[6];
    const float* bv = (const float*)d_in[7];
    const float* Wo = (const float*)d_in[8];
    const float* bo = (const float*)d_in[9];
    const float* g1 = (const float*)d_in[10];
    const float* b1 = (const float*)d_in[11];
    const float* W1 = (const float*)d_in[12];
    const float* c1 = (const float*)d_in[13];
    const float* W2 = (const float*)d_in[14];
    const float* c2 = (const float*)d_in[15];
    const float* g2 = (const float*)d_in[16];
    const float* b2 = (const float*)d_in[17];
    float* out = (float*)d_out;

    float *proj, *x1, *ff2;
    cudaGetSymbolAddress((void**)&proj, g_proj);
    cudaGetSymbolAddress((void**)&x1,   g_x1);
    cudaGetSymbolAddress((void**)&ff2,  g_ff2);

    unsigned short *ax, *qs, *ks, *vs, *aatt, *ax1, *aff1;
    unsigned short *wq2, *wk2, *wv2, *wo2, *w12, *w22;
    cudaGetSymbolAddress((void**)&ax,   g_ax);
    cudaGetSymbolAddress((void**)&qs,   g_qs);
    cudaGetSymbolAddress((void**)&ks,   g_ks);
    cudaGetSymbolAddress((void**)&vs,   g_vs);
    cudaGetSymbolAddress((void**)&aatt, g_aatt);
    cudaGetSymbolAddress((void**)&ax1,  g_ax1);
    cudaGetSymbolAddress((void**)&aff1, g_aff1);
    cudaGetSymbolAddress((void**)&wq2,  g_wq);
    cudaGetSymbolAddress((void**)&wk2,  g_wk);
    cudaGetSymbolAddress((void**)&wv2,  g_wv);
    cudaGetSymbolAddress((void**)&wo2,  g_wo);
    cudaGetSymbolAddress((void**)&w12,  g_w1);
    cudaGetSymbolAddress((void**)&w22,  g_w2);

    cudaFuncSetAttribute(mma_gemm_kernel,
                         cudaFuncAttributeMaxDynamicSharedMemorySize, GEMM_SMEM);
    cudaFuncSetAttribute(attn_tc_kernel,
                         cudaFuncAttributeMaxDynamicSharedMemorySize, ATT2_SMEM);

    const dim3 blk(256);
    const dim3 wblk(32, 8);
    const dim3 gD(DD/128, MM/128);       // N=1024 GEMMs
    const dim3 gF(FF/128, MM/128);       // N=4096 GEMM

    convert_w_kernel<<<dim3(DD/32, DD/32), wblk>>>(Wq, wq2, DD, DD);
    convert_w_kernel<<<dim3(DD/32, DD/32), wblk>>>(Wk, wk2, DD, DD);
    convert_w_kernel<<<dim3(DD/32, DD/32), wblk>>>(Wv, wv2, DD, DD);
    convert_w_kernel<<<dim3(DD/32, DD/32), wblk>>>(Wo, wo2, DD, DD);
    convert_a_kernel<<<(int)(((size_t)MM*DD/4 + 255)/256), blk>>>(x, ax, DD);

    // QKV projections -> pre-split bf16 layouts
    mma_gemm_kernel<<<gD, blk, GEMM_SMEM>>>(ax, wq2, bq, nullptr, qs, DD, 3*DD, 2);
    mma_gemm_kernel<<<gD, blk, GEMM_SMEM>>>(ax, wk2, bk, nullptr, ks, DD, 3*DD, 3);
    mma_gemm_kernel<<<gD, blk, GEMM_SMEM>>>(ax, wv2, bv, nullptr, vs, DD, 3*DD, 4);

    // attention (pre-split inputs, writes split A'')
    attn_tc_kernel<<<dim3(SS/64, BB*HH), 128, ATT2_SMEM>>>(qs, ks, vs, aatt);

    // output projection + residual LN (fused split of x1)
    mma_gemm_kernel<<<gD, blk, GEMM_SMEM>>>(aatt, wo2, bo, proj, nullptr, DD, 3*DD, 0);
    add_ln_kernel<<<MM, blk>>>(x, proj, g1, b1, x1, ax1);

    // FFN
    convert_w_kernel<<<dim3(FF/32, DD/32), wblk>>>(W1, w12, DD, FF);
    mma_gemm_kernel<<<gF, blk, GEMM_SMEM>>>(ax1, w12, c1, nullptr, aff1, FF, 3*DD, 1);
    convert_w_kernel<<<dim3(DD/32, FF/32), wblk>>>(W2, w22, FF, DD);
    mma_gemm_kernel<<<gD, blk, GEMM_SMEM>>>(aff1, w22, c2, ff2, nullptr, DD, 3*FF, 0);
    add_ln_kernel<<<MM, blk>>>(x1, ff2, g2, b2, out, nullptr);
}

// round 10
// speedup vs baseline: 2.0359x; 1.3316x over previous
#include <cuda_runtime.h>
#include <cuda_bf16.h>
#include <cuda_fp16.h>
#include <cstdint>
#include <cstddef>

// Problem constants
#define BB 4
#define SS 2048
#define DD 1024
#define HH 16
#define DKK 64
#define FF 4096
#define MM (BB*SS)          // 8192 rows

// ---------------------------------------------------------------------------
// Scratch (no allocations allowed -> __device__ globals)
// ---------------------------------------------------------------------------
__device__ float g_proj[(size_t)MM*DD];
__device__ float g_x1  [(size_t)MM*DD];
__device__ float g_ff2 [(size_t)MM*DD];

// fp16 2-term GEMM operand buffers: A'' = [hi | lo], B'' = [hi | hi]
__device__ unsigned short g_ax  [(size_t)MM*2*DD];   // x        fp16 [hi,lo]
__device__ unsigned short g_aatt[(size_t)MM*2*DD];   // attn out fp16 [hi,lo]
__device__ unsigned short g_ax1 [(size_t)MM*2*DD];   // x1       fp16 [hi,lo]
__device__ unsigned short g_aff1[(size_t)MM*2*FF];   // relu ff1 fp16 [hi,lo]
__device__ unsigned short g_wq  [(size_t)DD*2*DD];   // fp16 [hi,hi]
__device__ unsigned short g_wk  [(size_t)DD*2*DD];
__device__ unsigned short g_wv  [(size_t)DD*2*DD];
__device__ unsigned short g_wo  [(size_t)DD*2*DD];
__device__ unsigned short g_w1  [(size_t)FF*2*DD];   // [N=F, 2K]
__device__ unsigned short g_w2  [(size_t)DD*2*FF];   // [N=D, 2K]

// bf16 3-term attention operand buffers (precision-critical path)
__device__ unsigned short g_qs  [(size_t)MM*3*DD];   // q*1/8  bf16 (hi,hi,lo)
__device__ unsigned short g_ks  [(size_t)MM*3*DD];   // k      bf16 (hi,lo,hi)
__device__ unsigned short g_vs  [(size_t)MM*2*DD];   // v      bf16 (hi | lo)

// ---------------------------------------------------------------------------
// Helpers
// ---------------------------------------------------------------------------
__device__ __forceinline__ uint32_t smem_u32(const void* p) {
    uint32_t a;
    asm("{ .reg .u64 t; cvta.to.shared.u64 t, %1; cvt.u32.u64 %0, t; }"
        : "=r"(a) : "l"(p));
    return a;
}

__device__ __forceinline__ void cp16(uint32_t dst, const void* src) {
    asm volatile("cp.async.cg.shared.global [%0], [%1], 16;" :: "r"(dst), "l"(src));
}

#define CP_COMMIT() asm volatile("cp.async.commit_group;")
#define CP_WAIT2()  asm volatile("cp.async.wait_group 2;" ::: "memory")

#define LDSM4(r0, r1, r2, r3, addr) \
    asm volatile("ldmatrix.sync.aligned.m8n8.x4.shared.b16 {%0,%1,%2,%3}, [%4];" \
        : "=r"(r0), "=r"(r1), "=r"(r2), "=r"(r3) : "r"(addr))

#define LDSM4T(r0, r1, r2, r3, addr) \
    asm volatile("ldmatrix.sync.aligned.m8n8.x4.trans.shared.b16 {%0,%1,%2,%3}, [%4];" \
        : "=r"(r0), "=r"(r1), "=r"(r2), "=r"(r3) : "r"(addr))

// bf16 MMA (attention)
#define MMA16816B(d, a, b0v, b1v) \
    asm volatile("mma.sync.aligned.m16n8k16.row.col.f32.bf16.bf16.f32 " \
        "{%0,%1,%2,%3}, {%4,%5,%6,%7}, {%8,%9}, {%0,%1,%2,%3};" \
        : "+f"((d)[0]), "+f"((d)[1]), "+f"((d)[2]), "+f"((d)[3]) \
        : "r"((a)[0]), "r"((a)[1]), "r"((a)[2]), "r"((a)[3]), "r"(b0v), "r"(b1v))

// fp16 MMA (dense GEMMs)
#define MMA16816F(d, a, b0v, b1v) \
    asm volatile("mma.sync.aligned.m16n8k16.row.col.f32.f16.f16.f32 " \
        "{%0,%1,%2,%3}, {%4,%5,%6,%7}, {%8,%9}, {%0,%1,%2,%3};" \
        : "+f"((d)[0]), "+f"((d)[1]), "+f"((d)[2]), "+f"((d)[3]) \
        : "r"((a)[0]), "r"((a)[1]), "r"((a)[2]), "r"((a)[3]), "r"(b0v), "r"(b1v))

__device__ __forceinline__ unsigned short f2bf_bits(float f) {
    __nv_bfloat16 h = __float2bfloat16(f);
    return *reinterpret_cast<unsigned short*>(&h);
}
__device__ __forceinline__ void bfsplit(float x, unsigned short& h, unsigned short& l) {
    h = f2bf_bits(x);
    __nv_bfloat16 hb = *reinterpret_cast<__nv_bfloat16*>(&h);
    l = f2bf_bits(x - __bfloat162float(hb));
}
__device__ __forceinline__ unsigned short f2h_bits(float f) {
    __half h = __float2half(f);
    return *reinterpret_cast<unsigned short*>(&h);
}
__device__ __forceinline__ void hsplit(float x, unsigned short& h, unsigned short& l) {
    h = f2h_bits(x);
    __half hb = *reinterpret_cast<__half*>(&h);
    l = f2h_bits(x - __half2float(hb));
}

// ---------------------------------------------------------------------------
// fp32 -> fp16 [hi | lo] K-expansion for activations. A''[m, 2K].
// ---------------------------------------------------------------------------
__global__ __launch_bounds__(256) void convert_a_kernel(
    const float* __restrict__ X, unsigned short* __restrict__ A, int K)
{
    size_t idx = (size_t)blockIdx.x * blockDim.x + threadIdx.x;
    size_t total = (size_t)MM * K / 4;
    if (idx >= total) return;
    size_t e = idx * 4;
    size_t m = e / K;
    int k = (int)(e % K);
    float4 v = *(const float4*)(X + e);
    unsigned short h0, h1, h2, h3, l0, l1, l2, l3;
    hsplit(v.x, h0, l0); hsplit(v.y, h1, l1);
    hsplit(v.z, h2, l2); hsplit(v.w, h3, l3);
    uint2 hp = make_uint2((uint32_t)h0 | ((uint32_t)h1 << 16),
                          (uint32_t)h2 | ((uint32_t)h3 << 16));
    uint2 lp = make_uint2((uint32_t)l0 | ((uint32_t)l1 << 16),
                          (uint32_t)l2 | ((uint32_t)l3 << 16));
    size_t ob = m * (size_t)(2 * K);
    *(uint2*)(A + ob + k)     = hp;
    *(uint2*)(A + ob + K + k) = lp;
}

// ---------------------------------------------------------------------------
// W[K,N] fp32 -> B''[N, 2K] fp16 [hi | hi] (transposed, hi replicated).
// ---------------------------------------------------------------------------
__global__ __launch_bounds__(256) void convert_w_kernel(
    const float* __restrict__ W, unsigned short* __restrict__ Bm, int K, int N)
{
    __shared__ float tile[32][33];
    const int n0 = blockIdx.x * 32;
    const int k0 = blockIdx.y * 32;
    for (int i = threadIdx.y; i < 32; i += 8)
        tile[i][threadIdx.x] = W[(size_t)(k0 + i) * N + n0 + threadIdx.x];
    __syncthreads();
    for (int i = threadIdx.y; i < 32; i += 8) {
        const int n = n0 + i;
        const int k = k0 + threadIdx.x;
        unsigned short h = f2h_bits(tile[threadIdx.x][i]);
        size_t ob = (size_t)n * (2 * K);
        Bm[ob + k]     = h;
        Bm[ob + K + k] = h;
    }
}

// ---------------------------------------------------------------------------
// mma.sync fp16 GEMM: BM=BN=128, BK=32, 3-stage cp.async, 256 threads
// (8 warps 2x4, warp tile 64x32), __launch_bounds__(256, 2).
// C = A''[M,K2] @ B''[N,K2]^T + bias. Epilogue modes:
//   0: fp32 C = acc + bias                         -> Cf[m][N]
//   1: relu -> fp16 [hi,lo]                        -> Cs[m][2N]
//   2: (acc+bias)*0.125 -> bf16 (hi,hi,lo)  [Q]    -> Cs[m][3N]
//   3: bf16 (hi,lo,hi)                      [K]    -> Cs[m][3N]
//   4: bf16 (hi | lo)                       [V]    -> Cs[m][2N]
// ---------------------------------------------------------------------------
#define BK 32
#define NSTAGE 3
#define ROWB 80
#define B_OFF (128*ROWB)
#define STG_B (2*B_OFF)
#define GEMM_SMEM (NSTAGE*STG_B)    // 61440

__global__ __launch_bounds__(256, 2) void mma_gemm_kernel(
    const unsigned short* __restrict__ Au, const unsigned short* __restrict__ Bu,
    const float* __restrict__ bias, float* __restrict__ Cf,
    unsigned short* __restrict__ Cs, int N, int K2, int mode)
{
    extern __shared__ char smem[];
    const uint32_t sb = smem_u32(smem);
    const int tid = threadIdx.x;
    const int wid = tid >> 5, lane = tid & 31;
    const int wm = wid >> 2, wn = wid & 3;
    const int mb = blockIdx.y, nb = blockIdx.x;

    const int r0 = tid >> 2, cc = tid & 3;
    const unsigned short* aS = Au + ((size_t)(mb * 128) + r0) * K2 + cc * 8;
    const unsigned short* bS = Bu + ((size_t)(nb * 128) + r0) * K2 + cc * 8;
    const size_t rowskip = (size_t)64 * K2;
    const uint32_t dOff = (uint32_t)(r0 * ROWB + cc * 16);

    float acc[4][4][4];
    #pragma unroll
    for (int i = 0; i < 4; i++)
        #pragma unroll
        for (int j = 0; j < 4; j++)
            #pragma unroll
            for (int r = 0; r < 4; r++) acc[i][j][r] = 0.f;

    const int nc = K2 / BK;

    auto LOAD = [&](int s, int c) {
        const uint32_t d = sb + s * STG_B + dOff;
        const unsigned short* a = aS + (size_t)c * BK;
        const unsigned short* b = bS + (size_t)c * BK;
        cp16(d,                    a);
        cp16(d + 64 * ROWB,        a + rowskip);
        cp16(d + B_OFF,            b);
        cp16(d + B_OFF + 64*ROWB,  b + rowskip);
    };

    LOAD(0, 0); CP_COMMIT();
    LOAD(1, 1); CP_COMMIT();

    const uint32_t aRow = (uint32_t)(wm * 64 + (lane & 15));
    const uint32_t aK   = ((lane >> 4) & 1) * 16;
    const uint32_t bRow = (uint32_t)(wn * 32 + ((lane >> 4) & 1) * 8 + (lane & 7));
    const uint32_t bK   = ((lane >> 3) & 1) * 16;

    for (int c = 0; c < nc; c++) {
        if (c + 2 < nc) LOAD((c + 2) % NSTAGE, c + 2);
        CP_COMMIT();
        CP_WAIT2();
        __syncthreads();
        const uint32_t base = sb + (c % NSTAGE) * STG_B;
        #pragma unroll
        for (int ks = 0; ks < 2; ks++) {
            uint32_t af[4][4], bf[2][4];
            #pragma unroll
            for (int mt = 0; mt < 4; mt++) {
                const uint32_t ad = base + (aRow + mt * 16) * ROWB + ks * 32 + aK;
                LDSM4(af[mt][0], af[mt][1], af[mt][2], af[mt][3], ad);
            }
            #pragma unroll
            for (int j = 0; j < 2; j++) {
                const uint32_t bd = base + B_OFF + (bRow + j * 16) * ROWB + ks * 32 + bK;
                LDSM4(bf[j][0], bf[j][1], bf[j][2], bf[j][3], bd);
            }
            #pragma unroll
            for (int mt = 0; mt < 4; mt++)
                #pragma unroll
                for (int nt = 0; nt < 4; nt++)
                    MMA16816F(acc[mt][nt], af[mt],
                              bf[nt >> 1][(nt & 1) * 2], bf[nt >> 1][(nt & 1) * 2 + 1]);
        }
        __syncthreads();
    }

    // ---------------- epilogue (fused conversions) ----------------
    const int row0 = mb * 128 + wm * 64 + (lane >> 2);
    const int col0 = nb * 128 + wn * 32 + (lane & 3) * 2;
    #pragma unroll
    for (int mt = 0; mt < 4; mt++) {
        const int r1 = row0 + mt * 16;
        const int r2 = r1 + 8;
        #pragma unroll
        for (int nt = 0; nt < 4; nt++) {
            const int cn = col0 + nt * 8;
            const float bx = __ldg(bias + cn), by = __ldg(bias + cn + 1);
            float o10 = acc[mt][nt][0] + bx, o11 = acc[mt][nt][1] + by;
            float o20 = acc[mt][nt][2] + bx, o21 = acc[mt][nt][3] + by;
            if (mode == 0) {
                *(float2*)(Cf + (size_t)r1 * N + cn) = make_float2(o10, o11);
                *(float2*)(Cf + (size_t)r2 * N + cn) = make_float2(o20, o21);
            } else if (mode == 1) {
                // relu -> fp16 [hi | lo]
                o10 = fmaxf(o10, 0.f); o11 = fmaxf(o11, 0.f);
                o20 = fmaxf(o20, 0.f); o21 = fmaxf(o21, 0.f);
                unsigned short h0, l0, h1, l1;
                hsplit(o10, h0, l0); hsplit(o11, h1, l1);
                unsigned short* p = Cs + (size_t)r1 * (2 * N) + cn;
                *(uint32_t*)p       = (uint32_t)h0 | ((uint32_t)h1 << 16);
                *(uint32_t*)(p + N) = (uint32_t)l0 | ((uint32_t)l1 << 16);
                hsplit(o20, h0, l0); hsplit(o21, h1, l1);
                p = Cs + (size_t)r2 * (2 * N) + cn;
                *(uint32_t*)p       = (uint32_t)h0 | ((uint32_t)h1 << 16);
                *(uint32_t*)(p + N) = (uint32_t)l0 | ((uint32_t)l1 << 16);
            } else if (mode == 4) {
                // V: bf16 [hi | lo]
                unsigned short h0, l0, h1, l1;
                bfsplit(o10, h0, l0); bfsplit(o11, h1, l1);
                unsigned short* p = Cs + (size_t)r1 * (2 * N) + cn;
                *(uint32_t*)p       = (uint32_t)h0 | ((uint32_t)h1 << 16);
                *(uint32_t*)(p + N) = (uint32_t)l0 | ((uint32_t)l1 << 16);
                bfsplit(o20, h0, l0); bfsplit(o21, h1, l1);
                p = Cs + (size_t)r2 * (2 * N) + cn;
                *(uint32_t*)p       = (uint32_t)h0 | ((uint32_t)h1 << 16);
                *(uint32_t*)(p + N) = (uint32_t)l0 | ((uint32_t)l1 << 16);
            } else {
                // Q (mode 2): (acc)*0.125 -> bf16 (hi,hi,lo); K (mode 3): bf16 (hi,lo,hi)
                if (mode == 2) {
                    o10 *= 0.125f; o11 *= 0.125f; o20 *= 0.125f; o21 *= 0.125f;
                }
                unsigned short h0, l0, h1, l1;
                bfsplit(o10, h0, l0); bfsplit(o11, h1, l1);
                uint32_t hp = (uint32_t)h0 | ((uint32_t)h1 << 16);
                uint32_t lp = (uint32_t)l0 | ((uint32_t)l1 << 16);
                unsigned short* p = Cs + (size_t)r1 * (3 * N) + cn;
                if (mode == 3) { *(uint32_t*)p = hp; *(uint32_t*)(p + N) = lp; *(uint32_t*)(p + 2 * N) = hp; }
                else           { *(uint32_t*)p = hp; *(uint32_t*)(p + N) = hp; *(uint32_t*)(p + 2 * N) = lp; }
                bfsplit(o20, h0, l0); bfsplit(o21, h1, l1);
                hp = (uint32_t)h0 | ((uint32_t)h1 << 16);
                lp = (uint32_t)l0 | ((uint32_t)l1 << 16);
                p = Cs + (size_t)r2 * (3 * N) + cn;
                if (mode == 3) { *(uint32_t*)p = hp; *(uint32_t*)(p + N) = lp; *(uint32_t*)(p + 2 * N) = hp; }
                else           { *(uint32_t*)p = hp; *(uint32_t*)(p + N) = hp; *(uint32_t*)(p + 2 * N) = lp; }
            }
        }
    }
}

// ---------------------------------------------------------------------------
// Tensor-core flash attention (bf16 3-term, unchanged math). Inputs PRE-SPLIT:
//   Qg [m][3D]: (hi,hi,lo) scaled 1/8; Kg [m][3D]: (hi,lo,hi); Vg [m][2D]: hi|lo
// Epilogue writes fp16 [hi | lo] into g_aatt[m][2D] for the Wo GEMM.
// ---------------------------------------------------------------------------
#define AQROWB 400
#define AVROWB 144
#define ATT2_SMEM (2*64*AQROWB + 2*64*AVROWB)   // 69632

__global__ __launch_bounds__(128) void attn_tc_kernel(
    const unsigned short* __restrict__ Qg, const unsigned short* __restrict__ Kg,
    const unsigned short* __restrict__ Vg, unsigned short* __restrict__ Aout)
{
    extern __shared__ char sm8[];
    char* Qs = sm8;
    char* Ks = Qs + 64 * AQROWB;
    char* Vh = Ks + 64 * AQROWB;
    char* Vl = Vh + 64 * AVROWB;
    const uint32_t qsb = smem_u32(Qs), ksb = smem_u32(Ks);
    const uint32_t vhb = smem_u32(Vh), vlb = smem_u32(Vl);

    const int tid = threadIdx.x, wid = tid >> 5, lane = tid & 31;
    const int q0 = blockIdx.x * 64;
    const int b = blockIdx.y >> 4, h = blockIdx.y & 15;
    const size_t bS = (size_t)b * SS;

    // ---- load Q tile ----
    {
        const int r = tid >> 1, half = tid & 1;
        const unsigned short* src = Qg + (bS + q0 + r) * (size_t)(3 * DD) + h * 64;
        char* drow = Qs + r * AQROWB;
        #pragma unroll
        for (int ch = 0; ch < 12; ch++) {
            const int c = half * 12 + ch;
            const int seg = c >> 3, off = c & 7;
            *(uint4*)(drow + (seg * 64 + off * 8) * 2) =
                *(const uint4*)(src + seg * DD + off * 8);
        }
    }
    __syncthreads();

    uint32_t qf[12][4];
    {
        const uint32_t ab = qsb + (wid * 16 + (lane & 15)) * AQROWB + ((lane >> 4) & 1) * 16;
        #pragma unroll
        for (int ks = 0; ks < 12; ks++)
            LDSM4(qf[ks][0], qf[ks][1], qf[ks][2], qf[ks][3], ab + ks * 32);
    }

    const uint32_t bRow = ((lane >> 4) & 1) * 8 + (lane & 7);
    const uint32_t bK   = ((lane >> 3) & 1) * 16;
    const uint32_t vLn  = (lane & 15);
    const uint32_t vCo  = ((lane >> 4) & 1) * 16;

    float O[8][4];
    #pragma unroll
    for (int j = 0; j < 8; j++)
        #pragma unroll
        for (int r = 0; r < 4; r++) O[j][r] = 0.f;
    float m0 = -1e30f, m1 = -1e30f, l0 = 0.f, l1 = 0.f;

    const int r0l = wid * 16 + (lane >> 2);
    const int r1l = r0l + 8;

    for (int kt = 0; kt <= blockIdx.x; kt++) {
        const int k0 = kt * 64;
        __syncthreads();
        {
            const int r = tid >> 1, half = tid & 1;
            const unsigned short* ksrc = Kg + (bS + k0 + r) * (size_t)(3 * DD) + h * 64;
            char* krow = Ks + r * AQROWB;
            #pragma unroll
            for (int ch = 0; ch < 12; ch++) {
                const int c = half * 12 + ch;
                const int seg = c >> 3, off = c & 7;
                *(uint4*)(krow + (seg * 64 + off * 8) * 2) =
                    *(const uint4*)(ksrc + seg * DD + off * 8);
            }
            const unsigned short* vsrc = Vg + (bS + k0 + r) * (size_t)(2 * DD)
                                            + half * DD + h * 64;
            char* vrow = (half ? Vl : Vh) + r * AVROWB;
            #pragma unroll
            for (int off = 0; off < 8; off++)
                *(uint4*)(vrow + off * 16) = *(const uint4*)(vsrc + off * 8);
        }
        __syncthreads();

        float s[8][4];
        #pragma unroll
        for (int j = 0; j < 8; j++)
            #pragma unroll
            for (int r = 0; r < 4; r++) s[j][r] = 0.f;
        #pragma unroll
        for (int ks = 0; ks < 12; ks++) {
            #pragma unroll
            for (int j16 = 0; j16 < 4; j16++) {
                uint32_t kf0, kf1, kf2, kf3;
                LDSM4(kf0, kf1, kf2, kf3,
                      ksb + (j16 * 16 + bRow) * AQROWB + ks * 32 + bK);
                MMA16816B(s[2 * j16],     qf[ks], kf0, kf1);
                MMA16816B(s[2 * j16 + 1], qf[ks], kf2, kf3);
            }
        }

        if (kt == (int)blockIdx.x) {
            #pragma unroll
            for (int j = 0; j < 8; j++) {
                const int c = j * 8 + 2 * (lane & 3);
                if (c     > r0l) s[j][0] = -1e30f;
                if (c + 1 > r0l) s[j][1] = -1e30f;
                if (c     > r1l) s[j][2] = -1e30f;
                if (c + 1 > r1l) s[j][3] = -1e30f;
            }
        }

        float mx0 = -1e30f, mx1 = -1e30f;
        #pragma unroll
        for (int j = 0; j < 8; j++) {
            mx0 = fmaxf(mx0, fmaxf(s[j][0], s[j][1]));
            mx1 = fmaxf(mx1, fmaxf(s[j][2], s[j][3]));
        }
        mx0 = fmaxf(mx0, __shfl_xor_sync(0xffffffffu, mx0, 1));
        mx0 = fmaxf(mx0, __shfl_xor_sync(0xffffffffu, mx0, 2));
        mx1 = fmaxf(mx1, __shfl_xor_sync(0xffffffffu, mx1, 1));
        mx1 = fmaxf(mx1, __shfl_xor_sync(0xffffffffu, mx1, 2));
        const float mn0 = fmaxf(m0, mx0), mn1 = fmaxf(m1, mx1);
        const float cr0 = __expf(m0 - mn0), cr1 = __expf(m1 - mn1);
        m0 = mn0; m1 = mn1;
        float sum0 = 0.f, sum1 = 0.f;
        #pragma unroll
        for (int j = 0; j < 8; j++) {
            s[j][0] = __expf(s[j][0] - mn0);
            s[j][1] = __expf(s[j][1] - mn0);
            s[j][2] = __expf(s[j][2] - mn1);
            s[j][3] = __expf(s[j][3] - mn1);
            sum0 += s[j][0] + s[j][1];
            sum1 += s[j][2] + s[j][3];
        }
        sum0 += __shfl_xor_sync(0xffffffffu, sum0, 1);
        sum0 += __shfl_xor_sync(0xffffffffu, sum0, 2);
        sum1 += __shfl_xor_sync(0xffffffffu, sum1, 1);
        sum1 += __shfl_xor_sync(0xffffffffu, sum1, 2);
        l0 = l0 * cr0 + sum0;
        l1 = l1 * cr1 + sum1;
        #pragma unroll
        for (int j = 0; j < 8; j++) {
            O[j][0] *= cr0; O[j][1] *= cr0;
            O[j][2] *= cr1; O[j][3] *= cr1;
        }

        uint32_t phi[4][4], plo[4][4];
        #pragma unroll
        for (int ks2 = 0; ks2 < 4; ks2++) {
            const int j0 = 2 * ks2, j1 = j0 + 1;
            unsigned short h00, l00, h01, l01, h10, l10, h11, l11;
            bfsplit(s[j0][0], h00, l00); bfsplit(s[j0][1], h01, l01);
            phi[ks2][0] = (uint32_t)h00 | ((uint32_t)h01 << 16);
            plo[ks2][0] = (uint32_t)l00 | ((uint32_t)l01 << 16);
            bfsplit(s[j0][2], h10, l10); bfsplit(s[j0][3], h11, l11);
            phi[ks2][1] = (uint32_t)h10 | ((uint32_t)h11 << 16);
            plo[ks2][1] = (uint32_t)l10 | ((uint32_t)l11 << 16);
            bfsplit(s[j1][0], h00, l00); bfsplit(s[j1][1], h01, l01);
            phi[ks2][2] = (uint32_t)h00 | ((uint32_t)h01 << 16);
            plo[ks2][2] = (uint32_t)l00 | ((uint32_t)l01 << 16);
            bfsplit(s[j1][2], h10, l10); bfsplit(s[j1][3], h11, l11);
            phi[ks2][3] = (uint32_t)h10 | ((uint32_t)h11 << 16);
            plo[ks2][3] = (uint32_t)l10 | ((uint32_t)l11 << 16);
        }

        #pragma unroll
        for (int ks2 = 0; ks2 < 4; ks2++) {
            const uint32_t rowOff = (ks2 * 16 + vLn);
            #pragma unroll
            for (int dj = 0; dj < 4; dj++) {
                uint32_t vh0, vh1, vh2, vh3, vl0, vl1, vl2, vl3;
                LDSM4T(vh0, vh1, vh2, vh3, vhb + rowOff * AVROWB + dj * 32 + vCo);
                LDSM4T(vl0, vl1, vl2, vl3, vlb + rowOff * AVROWB + dj * 32 + vCo);
                MMA16816B(O[2 * dj],     phi[ks2], vh0, vh1);
                MMA16816B(O[2 * dj + 1], phi[ks2], vh2, vh3);
                MMA16816B(O[2 * dj],     phi[ks2], vl0, vl1);
                MMA16816B(O[2 * dj + 1], phi[ks2], vl2, vl3);
                MMA16816B(O[2 * dj],     plo[ks2], vh0, vh1);
                MMA16816B(O[2 * dj + 1], plo[ks2], vh2, vh3);
            }
        }
    }

    // ---- epilogue: O/l -> fp16 [hi | lo] rows of g_aatt ----
    const float inv0 = 1.f / l0, inv1 = 1.f / l1;
    const size_t m0g = bS + (q0 + r0l);
    const size_t m1g = m0g + 8;
    const int cb = h * 64 + 2 * (lane & 3);
    unsigned short* out0 = Aout + m0g * (size_t)(2 * DD) + cb;
    unsigned short* out1 = Aout + m1g * (size_t)(2 * DD) + cb;
    #pragma unroll
    for (int j = 0; j < 8; j++) {
        const int d = j * 8;
        unsigned short ha, la, hb2, lb2;
        hsplit(O[j][0] * inv0, ha, la);
        hsplit(O[j][1] * inv0, hb2, lb2);
        *(uint32_t*)(out0 + d)      = (uint32_t)ha | ((uint32_t)hb2 << 16);
        *(uint32_t*)(out0 + DD + d) = (uint32_t)la | ((uint32_t)lb2 << 16);
        hsplit(O[j][2] * inv1, ha, la);
        hsplit(O[j][3] * inv1, hb2, lb2);
        *(uint32_t*)(out1 + d)      = (uint32_t)ha | ((uint32_t)hb2 << 16);
        *(uint32_t*)(out1 + DD + d) = (uint32_t)la | ((uint32_t)lb2 << 16);
    }
}

// ---------------------------------------------------------------------------
// out = LayerNorm(x + y) * gamma + beta; optional fused fp16 [hi|lo] split
// ---------------------------------------------------------------------------
__device__ __forceinline__ float block_sum(float v, float* sh)
{
    const int lane = threadIdx.x & 31, w = threadIdx.x >> 5;
    #pragma unroll
    for (int o = 16; o; o >>= 1) v += __shfl_xor_sync(0xffffffffu, v, o);
    if (lane == 0) sh[w] = v;
    __syncthreads();
    float r = (lane < 8) ? sh[lane] : 0.f;
    #pragma unroll
    for (int o = 4; o; o >>= 1) r += __shfl_xor_sync(0xffffffffu, r, o);
    if (threadIdx.x == 0) sh[0] = r;
    __syncthreads();
    r = sh[0];
    __syncthreads();
    return r;
}

__global__ __launch_bounds__(256) void add_ln_kernel(
    const float* __restrict__ X, const float* __restrict__ Y,
    const float* __restrict__ g, const float* __restrict__ bta,
    float* __restrict__ out, unsigned short* __restrict__ As)
{
    __shared__ float sh[32];
    const size_t row = blockIdx.x;
    const int t = threadIdx.x;
    const float4 xv = ((const float4*)(X + row * DD))[t];
    const float4 yv = ((const float4*)(Y + row * DD))[t];
    float v0 = xv.x + yv.x, v1 = xv.y + yv.y, v2 = xv.z + yv.z, v3 = xv.w + yv.w;
    const float mean = block_sum(v0 + v1 + v2 + v3, sh) * (1.f / DD);
    const float d0 = v0 - mean, d1 = v1 - mean, d2 = v2 - mean, d3 = v3 - mean;
    const float var = block_sum(d0*d0 + d1*d1 + d2*d2 + d3*d3, sh) * (1.f / DD);
    const float inv = rsqrtf(var + 1e-5f);
    const float4 gv = ((const float4*)g)[t];
    const float4 bv = ((const float4*)bta)[t];
    float4 o;
    o.x = d0 * inv * gv.x + bv.x;
    o.y = d1 * inv * gv.y + bv.y;
    o.z = d2 * inv * gv.z + bv.z;
    o.w = d3 * inv * gv.w + bv.w;
    ((float4*)(out + row * DD))[t] = o;
    if (As) {
        unsigned short h0, l0, h1, l1, h2, l2, h3, l3;
        hsplit(o.x, h0, l0); hsplit(o.y, h1, l1);
        hsplit(o.z, h2, l2); hsplit(o.w, h3, l3);
        uint2 hp = make_uint2((uint32_t)h0 | ((uint32_t)h1 << 16),
                              (uint32_t)h2 | ((uint32_t)h3 << 16));
        uint2 lp = make_uint2((uint32_t)l0 | ((uint32_t)l1 << 16),
                              (uint32_t)l2 | ((uint32_t)l3 << 16));
        unsigned short* p = As + row * (size_t)(2 * DD) + t * 4;
        *(uint2*)p        = hp;
        *(uint2*)(p + DD) = lp;
    }
}

// ---------------------------------------------------------------------------
// Launcher
// ---------------------------------------------------------------------------
extern "C" void kernel_launch(void* const* d_in, const int* in_sizes, int n_in,
                              void* d_out, int out_size)
{
    (void)in_sizes; (void)n_in; (void)out_size;
    const float* x  = (const float*)d_in[0];
    const float* Wq = (const float*)d_in[2];
    const float* bq = (const float*)d_in[3];
    const float* Wk = (const float*)d_in[4];
    const float* bk = (const float*)d_in[5];
    const float* Wv = (const float*)d_in[6];
    const float* bv = (const float*)d_in[7];
    const float* Wo = (const float*)d_in[8];
    const float* bo = (const float*)d_in[9];
    const float* g1 = (const float*)d_in[10];
    const float* b1 = (const float*)d_in[11];
    const float* W1 = (const float*)d_in[12];
    const float* c1 = (const float*)d_in[13];
    const float* W2 = (const float*)d_in[14];
    const float* c2 = (const float*)d_in[15];
    const float* g2 = (const float*)d_in[16];
    const float* b2 = (const float*)d_in[17];
    float* out = (float*)d_out;

    float *proj, *x1, *ff2;
    cudaGetSymbolAddress((void**)&proj, g_proj);
    cudaGetSymbolAddress((void**)&x1,   g_x1);
    cudaGetSymbolAddress((void**)&ff2,  g_ff2);

    unsigned short *ax, *qs, *ks, *vs, *aatt, *ax1, *aff1;
    unsigned short *wq2, *wk2, *wv2, *wo2, *w12, *w22;
    cudaGetSymbolAddress((void**)&ax,   g_ax);
    cudaGetSymbolAddress((void**)&qs,   g_qs);
    cudaGetSymbolAddress((void**)&ks,   g_ks);
    cudaGetSymbolAddress((void**)&vs,   g_vs);
    cudaGetSymbolAddress((void**)&aatt, g_aatt);
    cudaGetSymbolAddress((void**)&ax1,  g_ax1);
    cudaGetSymbolAddress((void**)&aff1, g_aff1);
    cudaGetSymbolAddress((void**)&wq2,  g_wq);
    cudaGetSymbolAddress((void**)&wk2,  g_wk);
    cudaGetSymbolAddress((void**)&wv2,  g_wv);
    cudaGetSymbolAddress((void**)&wo2,  g_wo);
    cudaGetSymbolAddress((void**)&w12,  g_w1);
    cudaGetSymbolAddress((void**)&w22,  g_w2);

    cudaFuncSetAttribute(mma_gemm_kernel,
                         cudaFuncAttributeMaxDynamicSharedMemorySize, GEMM_SMEM);
    cudaFuncSetAttribute(attn_tc_kernel,
                         cudaFuncAttributeMaxDynamicSharedMemorySize, ATT2_SMEM);

    const dim3 blk(256);
    const dim3 wblk(32, 8);
    const dim3 gD(DD/128, MM/128);       // N=1024 GEMMs
    const dim3 gF(FF/128, MM/128);       // N=4096 GEMM

    convert_w_kernel<<<dim3(DD/32, DD/32), wblk>>>(Wq, wq2, DD, DD);
    convert_w_kernel<<<dim3(DD/32, DD/32), wblk>>>(Wk, wk2, DD, DD);
    convert_w_kernel<<<dim3(DD/32, DD/32), wblk>>>(Wv, wv2, DD, DD);
    convert_w_kernel<<<dim3(DD/32, DD/32), wblk>>>(Wo, wo2, DD, DD);
    convert_a_kernel<<<(int)(((size_t)MM*DD/4 + 255)/256), blk>>>(x, ax, DD);

    // QKV projections (fp16 2-term GEMM) -> pre-split bf16 attention layouts
    mma_gemm_kernel<<<gD, blk, GEMM_SMEM>>>(ax, wq2, bq, nullptr, qs, DD, 2*DD, 2);
    mma_gemm_kernel<<<gD, blk, GEMM_SMEM>>>(ax, wk2, bk, nullptr, ks, DD, 2*DD, 3);
    mma_gemm_kernel<<<gD, blk, GEMM_SMEM>>>(ax, wv2, bv, nullptr, vs, DD, 2*DD, 4);

    // attention (bf16 3-term inside, writes fp16 [hi|lo] A'')
    attn_tc_kernel<<<dim3(SS/64, BB*HH), 128, ATT2_SMEM>>>(qs, ks, vs, aatt);

    // output projection + residual LN (fused fp16 split of x1)
    mma_gemm_kernel<<<gD, blk, GEMM_SMEM>>>(aatt, wo2, bo, proj, nullptr, DD, 2*DD, 0);
    add_ln_kernel<<<MM, blk>>>(x, proj, g1, b1, x1, ax1);

    // FFN
    convert_w_kernel<<<dim3(FF/32, DD/32), wblk>>>(W1, w12, DD, FF);
    mma_gemm_kernel<<<gF, blk, GEMM_SMEM>>>(ax1, w12, c1, nullptr, aff1, FF, 2*DD, 1);
    convert_w_kernel<<<dim3(DD/32, FF/32), wblk>>>(W2, w22, FF, DD);
    mma_gemm_kernel<<<gD, blk, GEMM_SMEM>>>(aff1, w22, c2, ff2, nullptr, DD, 2*FF, 0);
    add_ln_kernel<<<MM, blk>>>(x1, ff2, g2, b2, out, nullptr);
}

// round 11
// speedup vs baseline: 2.9884x; 1.4678x over previous
#include <cuda_runtime.h>
#include <cuda_bf16.h>
#include <cuda_fp16.h>
#include <cstdint>
#include <cstddef>

// Problem constants
#define BB 4
#define SS 2048
#define DD 1024
#define HH 16
#define DKK 64
#define FF 4096
#define MM (BB*SS)          // 8192 rows

// ---------------------------------------------------------------------------
// Scratch (no allocations allowed -> __device__ globals)
// ---------------------------------------------------------------------------
__device__ float g_proj[(size_t)MM*DD];
__device__ float g_x1  [(size_t)MM*DD];
__device__ float g_ff2 [(size_t)MM*DD];

// fp16 single-term GEMM operands
__device__ unsigned short g_ax  [(size_t)MM*DD];     // x        fp16
__device__ unsigned short g_aatt[(size_t)MM*DD];     // attn out fp16
__device__ unsigned short g_ax1 [(size_t)MM*DD];     // x1       fp16
__device__ unsigned short g_aff1[(size_t)MM*FF];     // relu ff1 fp16
__device__ unsigned short g_wq  [(size_t)DD*DD];     // W^T fp16
__device__ unsigned short g_wk  [(size_t)DD*DD];
__device__ unsigned short g_wv  [(size_t)DD*DD];
__device__ unsigned short g_wo  [(size_t)DD*DD];
__device__ unsigned short g_w1  [(size_t)FF*DD];     // [N=F, K=D]
__device__ unsigned short g_w2  [(size_t)DD*FF];     // [N=D, K=F]

// bf16 3-term attention operand buffers (precision-critical path)
__device__ unsigned short g_qs  [(size_t)MM*3*DD];   // q*1/8  bf16 (hi,hi,lo)
__device__ unsigned short g_ks  [(size_t)MM*3*DD];   // k      bf16 (hi,lo,hi)
__device__ unsigned short g_vs  [(size_t)MM*2*DD];   // v      bf16 (hi | lo)

// ---------------------------------------------------------------------------
// Helpers
// ---------------------------------------------------------------------------
__device__ __forceinline__ uint32_t smem_u32(const void* p) {
    uint32_t a;
    asm("{ .reg .u64 t; cvta.to.shared.u64 t, %1; cvt.u32.u64 %0, t; }"
        : "=r"(a) : "l"(p));
    return a;
}

__device__ __forceinline__ void cp16(uint32_t dst, const void* src) {
    asm volatile("cp.async.cg.shared.global [%0], [%1], 16;" :: "r"(dst), "l"(src));
}

#define CP_COMMIT() asm volatile("cp.async.commit_group;")
#define CP_WAIT2()  asm volatile("cp.async.wait_group 2;" ::: "memory")

#define LDSM4(r0, r1, r2, r3, addr) \
    asm volatile("ldmatrix.sync.aligned.m8n8.x4.shared.b16 {%0,%1,%2,%3}, [%4];" \
        : "=r"(r0), "=r"(r1), "=r"(r2), "=r"(r3) : "r"(addr))

#define LDSM4T(r0, r1, r2, r3, addr) \
    asm volatile("ldmatrix.sync.aligned.m8n8.x4.trans.shared.b16 {%0,%1,%2,%3}, [%4];" \
        : "=r"(r0), "=r"(r1), "=r"(r2), "=r"(r3) : "r"(addr))

// bf16 MMA (attention)
#define MMA16816B(d, a, b0v, b1v) \
    asm volatile("mma.sync.aligned.m16n8k16.row.col.f32.bf16.bf16.f32 " \
        "{%0,%1,%2,%3}, {%4,%5,%6,%7}, {%8,%9}, {%0,%1,%2,%3};" \
        : "+f"((d)[0]), "+f"((d)[1]), "+f"((d)[2]), "+f"((d)[3]) \
        : "r"((a)[0]), "r"((a)[1]), "r"((a)[2]), "r"((a)[3]), "r"(b0v), "r"(b1v))

// fp16 MMA (dense GEMMs)
#define MMA16816F(d, a, b0v, b1v) \
    asm volatile("mma.sync.aligned.m16n8k16.row.col.f32.f16.f16.f32 " \
        "{%0,%1,%2,%3}, {%4,%5,%6,%7}, {%8,%9}, {%0,%1,%2,%3};" \
        : "+f"((d)[0]), "+f"((d)[1]), "+f"((d)[2]), "+f"((d)[3]) \
        : "r"((a)[0]), "r"((a)[1]), "r"((a)[2]), "r"((a)[3]), "r"(b0v), "r"(b1v))

__device__ __forceinline__ unsigned short f2bf_bits(float f) {
    __nv_bfloat16 h = __float2bfloat16(f);
    return *reinterpret_cast<unsigned short*>(&h);
}
__device__ __forceinline__ void bfsplit(float x, unsigned short& h, unsigned short& l) {
    h = f2bf_bits(x);
    __nv_bfloat16 hb = *reinterpret_cast<__nv_bfloat16*>(&h);
    l = f2bf_bits(x - __bfloat162float(hb));
}
__device__ __forceinline__ unsigned short f2h_bits(float f) {
    __half h = __float2half(f);
    return *reinterpret_cast<unsigned short*>(&h);
}

// ---------------------------------------------------------------------------
// fp32 -> fp16 single-term conversion for activations. A[m, K].
// ---------------------------------------------------------------------------
__global__ __launch_bounds__(256) void convert_a_kernel(
    const float* __restrict__ X, unsigned short* __restrict__ A, int K)
{
    size_t idx = (size_t)blockIdx.x * blockDim.x + threadIdx.x;
    size_t total = (size_t)MM * K / 4;
    if (idx >= total) return;
    size_t e = idx * 4;
    float4 v = *(const float4*)(X + e);
    uint2 hp = make_uint2((uint32_t)f2h_bits(v.x) | ((uint32_t)f2h_bits(v.y) << 16),
                          (uint32_t)f2h_bits(v.z) | ((uint32_t)f2h_bits(v.w) << 16));
    *(uint2*)(A + e) = hp;
}

// ---------------------------------------------------------------------------
// W[K,N] fp32 -> B[N, K] fp16 (transposed).
// ---------------------------------------------------------------------------
__global__ __launch_bounds__(256) void convert_w_kernel(
    const float* __restrict__ W, unsigned short* __restrict__ Bm, int K, int N)
{
    __shared__ float tile[32][33];
    const int n0 = blockIdx.x * 32;
    const int k0 = blockIdx.y * 32;
    for (int i = threadIdx.y; i < 32; i += 8)
        tile[i][threadIdx.x] = W[(size_t)(k0 + i) * N + n0 + threadIdx.x];
    __syncthreads();
    for (int i = threadIdx.y; i < 32; i += 8) {
        const int n = n0 + i;
        const int k = k0 + threadIdx.x;
        Bm[(size_t)n * K + k] = f2h_bits(tile[threadIdx.x][i]);
    }
}

// ---------------------------------------------------------------------------
// mma.sync fp16 GEMM: BM=BN=128, BK=32, 3-stage cp.async, 256 threads
// (8 warps 2x4, warp tile 64x32), __launch_bounds__(256, 2).
// C = A[M,K] @ B[N,K]^T + bias. Epilogue modes:
//   0: fp32 C = acc + bias                         -> Cf[m][N]
//   1: relu -> fp16                                -> Cs[m][N]
//   2: (acc+bias)*0.125 -> bf16 (hi,hi,lo)  [Q]    -> Cs[m][3N]
//   3: bf16 (hi,lo,hi)                      [K]    -> Cs[m][3N]
//   4: bf16 (hi | lo)                       [V]    -> Cs[m][2N]
// ---------------------------------------------------------------------------
#define BK 32
#define NSTAGE 3
#define ROWB 80
#define B_OFF (128*ROWB)
#define STG_B (2*B_OFF)
#define GEMM_SMEM (NSTAGE*STG_B)    // 61440

__global__ __launch_bounds__(256, 2) void mma_gemm_kernel(
    const unsigned short* __restrict__ Au, const unsigned short* __restrict__ Bu,
    const float* __restrict__ bias, float* __restrict__ Cf,
    unsigned short* __restrict__ Cs, int N, int K2, int mode)
{
    extern __shared__ char smem[];
    const uint32_t sb = smem_u32(smem);
    const int tid = threadIdx.x;
    const int wid = tid >> 5, lane = tid & 31;
    const int wm = wid >> 2, wn = wid & 3;
    const int mb = blockIdx.y, nb = blockIdx.x;

    const int r0 = tid >> 2, cc = tid & 3;
    const unsigned short* aS = Au + ((size_t)(mb * 128) + r0) * K2 + cc * 8;
    const unsigned short* bS = Bu + ((size_t)(nb * 128) + r0) * K2 + cc * 8;
    const size_t rowskip = (size_t)64 * K2;
    const uint32_t dOff = (uint32_t)(r0 * ROWB + cc * 16);

    float acc[4][4][4];
    #pragma unroll
    for (int i = 0; i < 4; i++)
        #pragma unroll
        for (int j = 0; j < 4; j++)
            #pragma unroll
            for (int r = 0; r < 4; r++) acc[i][j][r] = 0.f;

    const int nc = K2 / BK;

    auto LOAD = [&](int s, int c) {
        const uint32_t d = sb + s * STG_B + dOff;
        const unsigned short* a = aS + (size_t)c * BK;
        const unsigned short* b = bS + (size_t)c * BK;
        cp16(d,                    a);
        cp16(d + 64 * ROWB,        a + rowskip);
        cp16(d + B_OFF,            b);
        cp16(d + B_OFF + 64*ROWB,  b + rowskip);
    };

    LOAD(0, 0); CP_COMMIT();
    LOAD(1, 1); CP_COMMIT();

    const uint32_t aRow = (uint32_t)(wm * 64 + (lane & 15));
    const uint32_t aK   = ((lane >> 4) & 1) * 16;
    const uint32_t bRow = (uint32_t)(wn * 32 + ((lane >> 4) & 1) * 8 + (lane & 7));
    const uint32_t bK   = ((lane >> 3) & 1) * 16;

    for (int c = 0; c < nc; c++) {
        if (c + 2 < nc) LOAD((c + 2) % NSTAGE, c + 2);
        CP_COMMIT();
        CP_WAIT2();
        __syncthreads();
        const uint32_t base = sb + (c % NSTAGE) * STG_B;
        #pragma unroll
        for (int ks = 0; ks < 2; ks++) {
            uint32_t af[4][4], bf[2][4];
            #pragma unroll
            for (int mt = 0; mt < 4; mt++) {
                const uint32_t ad = base + (aRow + mt * 16) * ROWB + ks * 32 + aK;
                LDSM4(af[mt][0], af[mt][1], af[mt][2], af[mt][3], ad);
            }
            #pragma unroll
            for (int j = 0; j < 2; j++) {
                const uint32_t bd = base + B_OFF + (bRow + j * 16) * ROWB + ks * 32 + bK;
                LDSM4(bf[j][0], bf[j][1], bf[j][2], bf[j][3], bd);
            }
            #pragma unroll
            for (int mt = 0; mt < 4; mt++)
                #pragma unroll
                for (int nt = 0; nt < 4; nt++)
                    MMA16816F(acc[mt][nt], af[mt],
                              bf[nt >> 1][(nt & 1) * 2], bf[nt >> 1][(nt & 1) * 2 + 1]);
        }
        __syncthreads();
    }

    // ---------------- epilogue (fused conversions) ----------------
    const int row0 = mb * 128 + wm * 64 + (lane >> 2);
    const int col0 = nb * 128 + wn * 32 + (lane & 3) * 2;
    #pragma unroll
    for (int mt = 0; mt < 4; mt++) {
        const int r1 = row0 + mt * 16;
        const int r2 = r1 + 8;
        #pragma unroll
        for (int nt = 0; nt < 4; nt++) {
            const int cn = col0 + nt * 8;
            const float bx = __ldg(bias + cn), by = __ldg(bias + cn + 1);
            float o10 = acc[mt][nt][0] + bx, o11 = acc[mt][nt][1] + by;
            float o20 = acc[mt][nt][2] + bx, o21 = acc[mt][nt][3] + by;
            if (mode == 0) {
                *(float2*)(Cf + (size_t)r1 * N + cn) = make_float2(o10, o11);
                *(float2*)(Cf + (size_t)r2 * N + cn) = make_float2(o20, o21);
            } else if (mode == 1) {
                // relu -> fp16 single
                o10 = fmaxf(o10, 0.f); o11 = fmaxf(o11, 0.f);
                o20 = fmaxf(o20, 0.f); o21 = fmaxf(o21, 0.f);
                *(uint32_t*)(Cs + (size_t)r1 * N + cn) =
                    (uint32_t)f2h_bits(o10) | ((uint32_t)f2h_bits(o11) << 16);
                *(uint32_t*)(Cs + (size_t)r2 * N + cn) =
                    (uint32_t)f2h_bits(o20) | ((uint32_t)f2h_bits(o21) << 16);
            } else if (mode == 4) {
                // V: bf16 [hi | lo]
                unsigned short h0, l0, h1, l1;
                bfsplit(o10, h0, l0); bfsplit(o11, h1, l1);
                unsigned short* p = Cs + (size_t)r1 * (2 * N) + cn;
                *(uint32_t*)p       = (uint32_t)h0 | ((uint32_t)h1 << 16);
                *(uint32_t*)(p + N) = (uint32_t)l0 | ((uint32_t)l1 << 16);
                bfsplit(o20, h0, l0); bfsplit(o21, h1, l1);
                p = Cs + (size_t)r2 * (2 * N) + cn;
                *(uint32_t*)p       = (uint32_t)h0 | ((uint32_t)h1 << 16);
                *(uint32_t*)(p + N) = (uint32_t)l0 | ((uint32_t)l1 << 16);
            } else {
                // Q (mode 2): (acc)*0.125 -> bf16 (hi,hi,lo); K (mode 3): bf16 (hi,lo,hi)
                if (mode == 2) {
                    o10 *= 0.125f; o11 *= 0.125f; o20 *= 0.125f; o21 *= 0.125f;
                }
                unsigned short h0, l0, h1, l1;
                bfsplit(o10, h0, l0); bfsplit(o11, h1, l1);
                uint32_t hp = (uint32_t)h0 | ((uint32_t)h1 << 16);
                uint32_t lp = (uint32_t)l0 | ((uint32_t)l1 << 16);
                unsigned short* p = Cs + (size_t)r1 * (3 * N) + cn;
                if (mode == 3) { *(uint32_t*)p = hp; *(uint32_t*)(p + N) = lp; *(uint32_t*)(p + 2 * N) = hp; }
                else           { *(uint32_t*)p = hp; *(uint32_t*)(p + N) = hp; *(uint32_t*)(p + 2 * N) = lp; }
                bfsplit(o20, h0, l0); bfsplit(o21, h1, l1);
                hp = (uint32_t)h0 | ((uint32_t)h1 << 16);
                lp = (uint32_t)l0 | ((uint32_t)l1 << 16);
                p = Cs + (size_t)r2 * (3 * N) + cn;
                if (mode == 3) { *(uint32_t*)p = hp; *(uint32_t*)(p + N) = lp; *(uint32_t*)(p + 2 * N) = hp; }
                else           { *(uint32_t*)p = hp; *(uint32_t*)(p + N) = hp; *(uint32_t*)(p + 2 * N) = lp; }
            }
        }
    }
}

// ---------------------------------------------------------------------------
// Tensor-core flash attention (bf16 3-term, unchanged math). Inputs PRE-SPLIT:
//   Qg [m][3D]: (hi,hi,lo) scaled 1/8; Kg [m][3D]: (hi,lo,hi); Vg [m][2D]: hi|lo
// Epilogue writes fp16 single into g_aatt[m][D] for the Wo GEMM.
// ---------------------------------------------------------------------------
#define AQROWB 400
#define AVROWB 144
#define ATT2_SMEM (2*64*AQROWB + 2*64*AVROWB)   // 69632

__global__ __launch_bounds__(128) void attn_tc_kernel(
    const unsigned short* __restrict__ Qg, const unsigned short* __restrict__ Kg,
    const unsigned short* __restrict__ Vg, unsigned short* __restrict__ Aout)
{
    extern __shared__ char sm8[];
    char* Qs = sm8;
    char* Ks = Qs + 64 * AQROWB;
    char* Vh = Ks + 64 * AQROWB;
    char* Vl = Vh + 64 * AVROWB;
    const uint32_t qsb = smem_u32(Qs), ksb = smem_u32(Ks);
    const uint32_t vhb = smem_u32(Vh), vlb = smem_u32(Vl);

    const int tid = threadIdx.x, wid = tid >> 5, lane = tid & 31;
    const int q0 = blockIdx.x * 64;
    const int b = blockIdx.y >> 4, h = blockIdx.y & 15;
    const size_t bS = (size_t)b * SS;

    // ---- load Q tile ----
    {
        const int r = tid >> 1, half = tid & 1;
        const unsigned short* src = Qg + (bS + q0 + r) * (size_t)(3 * DD) + h * 64;
        char* drow = Qs + r * AQROWB;
        #pragma unroll
        for (int ch = 0; ch < 12; ch++) {
            const int c = half * 12 + ch;
            const int seg = c >> 3, off = c & 7;
            *(uint4*)(drow + (seg * 64 + off * 8) * 2) =
                *(const uint4*)(src + seg * DD + off * 8);
        }
    }
    __syncthreads();

    uint32_t qf[12][4];
    {
        const uint32_t ab = qsb + (wid * 16 + (lane & 15)) * AQROWB + ((lane >> 4) & 1) * 16;
        #pragma unroll
        for (int ks = 0; ks < 12; ks++)
            LDSM4(qf[ks][0], qf[ks][1], qf[ks][2], qf[ks][3], ab + ks * 32);
    }

    const uint32_t bRow = ((lane >> 4) & 1) * 8 + (lane & 7);
    const uint32_t bK   = ((lane >> 3) & 1) * 16;
    const uint32_t vLn  = (lane & 15);
    const uint32_t vCo  = ((lane >> 4) & 1) * 16;

    float O[8][4];
    #pragma unroll
    for (int j = 0; j < 8; j++)
        #pragma unroll
        for (int r = 0; r < 4; r++) O[j][r] = 0.f;
    float m0 = -1e30f, m1 = -1e30f, l0 = 0.f, l1 = 0.f;

    const int r0l = wid * 16 + (lane >> 2);
    const int r1l = r0l + 8;

    for (int kt = 0; kt <= blockIdx.x; kt++) {
        const int k0 = kt * 64;
        __syncthreads();
        {
            const int r = tid >> 1, half = tid & 1;
            const unsigned short* ksrc = Kg + (bS + k0 + r) * (size_t)(3 * DD) + h * 64;
            char* krow = Ks + r * AQROWB;
            #pragma unroll
            for (int ch = 0; ch < 12; ch++) {
                const int c = half * 12 + ch;
                const int seg = c >> 3, off = c & 7;
                *(uint4*)(krow + (seg * 64 + off * 8) * 2) =
                    *(const uint4*)(ksrc + seg * DD + off * 8);
            }
            const unsigned short* vsrc = Vg + (bS + k0 + r) * (size_t)(2 * DD)
                                            + half * DD + h * 64;
            char* vrow = (half ? Vl : Vh) + r * AVROWB;
            #pragma unroll
            for (int off = 0; off < 8; off++)
                *(uint4*)(vrow + off * 16) = *(const uint4*)(vsrc + off * 8);
        }
        __syncthreads();

        float s[8][4];
        #pragma unroll
        for (int j = 0; j < 8; j++)
            #pragma unroll
            for (int r = 0; r < 4; r++) s[j][r] = 0.f;
        #pragma unroll
        for (int ks = 0; ks < 12; ks++) {
            #pragma unroll
            for (int j16 = 0; j16 < 4; j16++) {
                uint32_t kf0, kf1, kf2, kf3;
                LDSM4(kf0, kf1, kf2, kf3,
                      ksb + (j16 * 16 + bRow) * AQROWB + ks * 32 + bK);
                MMA16816B(s[2 * j16],     qf[ks], kf0, kf1);
                MMA16816B(s[2 * j16 + 1], qf[ks], kf2, kf3);
            }
        }

        if (kt == (int)blockIdx.x) {
            #pragma unroll
            for (int j = 0; j < 8; j++) {
                const int c = j * 8 + 2 * (lane & 3);
                if (c     > r0l) s[j][0] = -1e30f;
                if (c + 1 > r0l) s[j][1] = -1e30f;
                if (c     > r1l) s[j][2] = -1e30f;
                if (c + 1 > r1l) s[j][3] = -1e30f;
            }
        }

        float mx0 = -1e30f, mx1 = -1e30f;
        #pragma unroll
        for (int j = 0; j < 8; j++) {
            mx0 = fmaxf(mx0, fmaxf(s[j][0], s[j][1]));
            mx1 = fmaxf(mx1, fmaxf(s[j][2], s[j][3]));
        }
        mx0 = fmaxf(mx0, __shfl_xor_sync(0xffffffffu, mx0, 1));
        mx0 = fmaxf(mx0, __shfl_xor_sync(0xffffffffu, mx0, 2));
        mx1 = fmaxf(mx1, __shfl_xor_sync(0xffffffffu, mx1, 1));
        mx1 = fmaxf(mx1, __shfl_xor_sync(0xffffffffu, mx1, 2));
        const float mn0 = fmaxf(m0, mx0), mn1 = fmaxf(m1, mx1);
        const float cr0 = __expf(m0 - mn0), cr1 = __expf(m1 - mn1);
        m0 = mn0; m1 = mn1;
        float sum0 = 0.f, sum1 = 0.f;
        #pragma unroll
        for (int j = 0; j < 8; j++) {
            s[j][0] = __expf(s[j][0] - mn0);
            s[j][1] = __expf(s[j][1] - mn0);
            s[j][2] = __expf(s[j][2] - mn1);
            s[j][3] = __expf(s[j][3] - mn1);
            sum0 += s[j][0] + s[j][1];
            sum1 += s[j][2] + s[j][3];
        }
        sum0 += __shfl_xor_sync(0xffffffffu, sum0, 1);
        sum0 += __shfl_xor_sync(0xffffffffu, sum0, 2);
        sum1 += __shfl_xor_sync(0xffffffffu, sum1, 1);
        sum1 += __shfl_xor_sync(0xffffffffu, sum1, 2);
        l0 = l0 * cr0 + sum0;
        l1 = l1 * cr1 + sum1;
        #pragma unroll
        for (int j = 0; j < 8; j++) {
            O[j][0] *= cr0; O[j][1] *= cr0;
            O[j][2] *= cr1; O[j][3] *= cr1;
        }

        uint32_t phi[4][4], plo[4][4];
        #pragma unroll
        for (int ks2 = 0; ks2 < 4; ks2++) {
            const int j0 = 2 * ks2, j1 = j0 + 1;
            unsigned short h00, l00, h01, l01, h10, l10, h11, l11;
            bfsplit(s[j0][0], h00, l00); bfsplit(s[j0][1], h01, l01);
            phi[ks2][0] = (uint32_t)h00 | ((uint32_t)h01 << 16);
            plo[ks2][0] = (uint32_t)l00 | ((uint32_t)l01 << 16);
            bfsplit(s[j0][2], h10, l10); bfsplit(s[j0][3], h11, l11);
            phi[ks2][1] = (uint32_t)h10 | ((uint32_t)h11 << 16);
            plo[ks2][1] = (uint32_t)l10 | ((uint32_t)l11 << 16);
            bfsplit(s[j1][0], h00, l00); bfsplit(s[j1][1], h01, l01);
            phi[ks2][2] = (uint32_t)h00 | ((uint32_t)h01 << 16);
            plo[ks2][2] = (uint32_t)l00 | ((uint32_t)l01 << 16);
            bfsplit(s[j1][2], h10, l10); bfsplit(s[j1][3], h11, l11);
            phi[ks2][3] = (uint32_t)h10 | ((uint32_t)h11 << 16);
            plo[ks2][3] = (uint32_t)l10 | ((uint32_t)l11 << 16);
        }

        #pragma unroll
        for (int ks2 = 0; ks2 < 4; ks2++) {
            const uint32_t rowOff = (ks2 * 16 + vLn);
            #pragma unroll
            for (int dj = 0; dj < 4; dj++) {
                uint32_t vh0, vh1, vh2, vh3, vl0, vl1, vl2, vl3;
                LDSM4T(vh0, vh1, vh2, vh3, vhb + rowOff * AVROWB + dj * 32 + vCo);
                LDSM4T(vl0, vl1, vl2, vl3, vlb + rowOff * AVROWB + dj * 32 + vCo);
                MMA16816B(O[2 * dj],     phi[ks2], vh0, vh1);
                MMA16816B(O[2 * dj + 1], phi[ks2], vh2, vh3);
                MMA16816B(O[2 * dj],     phi[ks2], vl0, vl1);
                MMA16816B(O[2 * dj + 1], phi[ks2], vl2, vl3);
                MMA16816B(O[2 * dj],     plo[ks2], vh0, vh1);
                MMA16816B(O[2 * dj + 1], plo[ks2], vh2, vh3);
            }
        }
    }

    // ---- epilogue: O/l -> fp16 single rows of g_aatt ----
    const float inv0 = 1.f / l0, inv1 = 1.f / l1;
    const size_t m0g = bS + (q0 + r0l);
    const size_t m1g = m0g + 8;
    const int cb = h * 64 + 2 * (lane & 3);
    unsigned short* out0 = Aout + m0g * (size_t)DD + cb;
    unsigned short* out1 = Aout + m1g * (size_t)DD + cb;
    #pragma unroll
    for (int j = 0; j < 8; j++) {
        const int d = j * 8;
        *(uint32_t*)(out0 + d) = (uint32_t)f2h_bits(O[j][0] * inv0)
                               | ((uint32_t)f2h_bits(O[j][1] * inv0) << 16);
        *(uint32_t*)(out1 + d) = (uint32_t)f2h_bits(O[j][2] * inv1)
                               | ((uint32_t)f2h_bits(O[j][3] * inv1) << 16);
    }
}

// ---------------------------------------------------------------------------
// out = LayerNorm(x + y) * gamma + beta; optional fused fp16 single split
// ---------------------------------------------------------------------------
__device__ __forceinline__ float block_sum(float v, float* sh)
{
    const int lane = threadIdx.x & 31, w = threadIdx.x >> 5;
    #pragma unroll
    for (int o = 16; o; o >>= 1) v += __shfl_xor_sync(0xffffffffu, v, o);
    if (lane == 0) sh[w] = v;
    __syncthreads();
    float r = (lane < 8) ? sh[lane] : 0.f;
    #pragma unroll
    for (int o = 4; o; o >>= 1) r += __shfl_xor_sync(0xffffffffu, r, o);
    if (threadIdx.x == 0) sh[0] = r;
    __syncthreads();
    r = sh[0];
    __syncthreads();
    return r;
}

__global__ __launch_bounds__(256) void add_ln_kernel(
    const float* __restrict__ X, const float* __restrict__ Y,
    const float* __restrict__ g, const float* __restrict__ bta,
    float* __restrict__ out, unsigned short* __restrict__ As)
{
    __shared__ float sh[32];
    const size_t row = blockIdx.x;
    const int t = threadIdx.x;
    const float4 xv = ((const float4*)(X + row * DD))[t];
    const float4 yv = ((const float4*)(Y + row * DD))[t];
    float v0 = xv.x + yv.x, v1 = xv.y + yv.y, v2 = xv.z + yv.z, v3 = xv.w + yv.w;
    const float mean = block_sum(v0 + v1 + v2 + v3, sh) * (1.f / DD);
    const float d0 = v0 - mean, d1 = v1 - mean, d2 = v2 - mean, d3 = v3 - mean;
    const float var = block_sum(d0*d0 + d1*d1 + d2*d2 + d3*d3, sh) * (1.f / DD);
    const float inv = rsqrtf(var + 1e-5f);
    const float4 gv = ((const float4*)g)[t];
    const float4 bv = ((const float4*)bta)[t];
    float4 o;
    o.x = d0 * inv * gv.x + bv.x;
    o.y = d1 * inv * gv.y + bv.y;
    o.z = d2 * inv * gv.z + bv.z;
    o.w = d3 * inv * gv.w + bv.w;
    ((float4*)(out + row * DD))[t] = o;
    if (As) {
        uint2 hp = make_uint2((uint32_t)f2h_bits(o.x) | ((uint32_t)f2h_bits(o.y) << 16),
                              (uint32_t)f2h_bits(o.z) | ((uint32_t)f2h_bits(o.w) << 16));
        *(uint2*)(As + row * (size_t)DD + t * 4) = hp;
    }
}

// ---------------------------------------------------------------------------
// Launcher
// ---------------------------------------------------------------------------
extern "C" void kernel_launch(void* const* d_in, const int* in_sizes, int n_in,
                              void* d_out, int out_size)
{
    (void)in_sizes; (void)n_in; (void)out_size;
    const float* x  = (const float*)d_in[0];
    const float* Wq = (const float*)d_in[2];
    const float* bq = (const float*)d_in[3];
    const float* Wk = (const float*)d_in[4];
    const float* bk = (const float*)d_in[5];
    const float* Wv = (const float*)d_in[6];
    const float* bv = (const float*)d_in[7];
    const float* Wo = (const float*)d_in[8];
    const float* bo = (const float*)d_in[9];
    const float* g1 = (const float*)d_in[10];
    const float* b1 = (const float*)d_in[11];
    const float* W1 = (const float*)d_in[12];
    const float* c1 = (const float*)d_in[13];
    const float* W2 = (const float*)d_in[14];
    const float* c2 = (const float*)d_in[15];
    const float* g2 = (const float*)d_in[16];
    const float* b2 = (const float*)d_in[17];
    float* out = (float*)d_out;

    float *proj, *x1, *ff2;
    cudaGetSymbolAddress((void**)&proj, g_proj);
    cudaGetSymbolAddress((void**)&x1,   g_x1);
    cudaGetSymbolAddress((void**)&ff2,  g_ff2);

    unsigned short *ax, *qs, *ks, *vs, *aatt, *ax1, *aff1;
    unsigned short *wq2, *wk2, *wv2, *wo2, *w12, *w22;
    cudaGetSymbolAddress((void**)&ax,   g_ax);
    cudaGetSymbolAddress((void**)&qs,   g_qs);
    cudaGetSymbolAddress((void**)&ks,   g_ks);
    cudaGetSymbolAddress((void**)&vs,   g_vs);
    cudaGetSymbolAddress((void**)&aatt, g_aatt);
    cudaGetSymbolAddress((void**)&ax1,  g_ax1);
    cudaGetSymbolAddress((void**)&aff1, g_aff1);
    cudaGetSymbolAddress((void**)&wq2,  g_wq);
    cudaGetSymbolAddress((void**)&wk2,  g_wk);
    cudaGetSymbolAddress((void**)&wv2,  g_wv);
    cudaGetSymbolAddress((void**)&wo2,  g_wo);
    cudaGetSymbolAddress((void**)&w12,  g_w1);
    cudaGetSymbolAddress((void**)&w22,  g_w2);

    cudaFuncSetAttribute(mma_gemm_kernel,
                         cudaFuncAttributeMaxDynamicSharedMemorySize, GEMM_SMEM);
    cudaFuncSetAttribute(attn_tc_kernel,
                         cudaFuncAttributeMaxDynamicSharedMemorySize, ATT2_SMEM);

    const dim3 blk(256);
    const dim3 wblk(32, 8);
    const dim3 gD(DD/128, MM/128);       // N=1024 GEMMs
    const dim3 gF(FF/128, MM/128);       // N=4096 GEMM

    convert_w_kernel<<<dim3(DD/32, DD/32), wblk>>>(Wq, wq2, DD, DD);
    convert_w_kernel<<<dim3(DD/32, DD/32), wblk>>>(Wk, wk2, DD, DD);
    convert_w_kernel<<<dim3(DD/32, DD/32), wblk>>>(Wv, wv2, DD, DD);
    convert_w_kernel<<<dim3(DD/32, DD/32), wblk>>>(Wo, wo2, DD, DD);
    convert_a_kernel<<<(int)(((size_t)MM*DD/4 + 255)/256), blk>>>(x, ax, DD);

    // QKV projections (fp16 single-term GEMM, K=1024) -> pre-split bf16 layouts
    mma_gemm_kernel<<<gD, blk, GEMM_SMEM>>>(ax, wq2, bq, nullptr, qs, DD, DD, 2);
    mma_gemm_kernel<<<gD, blk, GEMM_SMEM>>>(ax, wk2, bk, nullptr, ks, DD, DD, 3);
    mma_gemm_kernel<<<gD, blk, GEMM_SMEM>>>(ax, wv2, bv, nullptr, vs, DD, DD, 4);

    // attention (bf16 3-term inside, writes fp16 single A)
    attn_tc_kernel<<<dim3(SS/64, BB*HH), 128, ATT2_SMEM>>>(qs, ks, vs, aatt);

    // output projection + residual LN (fused fp16 conversion of x1)
    mma_gemm_kernel<<<gD, blk, GEMM_SMEM>>>(aatt, wo2, bo, proj, nullptr, DD, DD, 0);
    add_ln_kernel<<<MM, blk>>>(x, proj, g1, b1, x1, ax1);

    // FFN
    convert_w_kernel<<<dim3(FF/32, DD/32), wblk>>>(W1, w12, DD, FF);
    mma_gemm_kernel<<<gF, blk, GEMM_SMEM>>>(ax1, w12, c1, nullptr, aff1, FF, DD, 1);
    convert_w_kernel<<<dim3(DD/32, FF/32), wblk>>>(W2, w22, FF, DD);
    mma_gemm_kernel<<<gD, blk, GEMM_SMEM>>>(aff1, w22, c2, ff2, nullptr, DD, FF, 0);
    add_ln_kernel<<<MM, blk>>>(x1, ff2, g2, b2, out, nullptr);
}

// round 12
// speedup vs baseline: 3.6718x; 1.2287x over previous
#include <cuda_runtime.h>
#include <cuda_bf16.h>
#include <cuda_fp16.h>
#include <cstdint>
#include <cstddef>

// Problem constants
#define BB 4
#define SS 2048
#define DD 1024
#define HH 16
#define DKK 64
#define FF 4096
#define MM (BB*SS)          // 8192 rows

// ---------------------------------------------------------------------------
// Scratch (no allocations allowed -> __device__ globals)
// ---------------------------------------------------------------------------
__device__ float g_proj[(size_t)MM*DD];
__device__ float g_x1  [(size_t)MM*DD];
__device__ float g_ff2 [(size_t)MM*DD];

// fp16 single-term GEMM operands
__device__ unsigned short g_ax  [(size_t)MM*DD];     // x        fp16
__device__ unsigned short g_aatt[(size_t)MM*DD];     // attn out fp16
__device__ unsigned short g_ax1 [(size_t)MM*DD];     // x1       fp16
__device__ unsigned short g_aff1[(size_t)MM*FF];     // relu ff1 fp16
__device__ unsigned short g_wq  [(size_t)DD*DD];     // W^T fp16
__device__ unsigned short g_wk  [(size_t)DD*DD];
__device__ unsigned short g_wv  [(size_t)DD*DD];
__device__ unsigned short g_wo  [(size_t)DD*DD];
__device__ unsigned short g_w1  [(size_t)FF*DD];     // [N=F, K=D]
__device__ unsigned short g_w2  [(size_t)DD*FF];     // [N=D, K=F]

// fp16 2-term attention operands
__device__ unsigned short g_qs  [(size_t)MM*2*DD];   // q*1/8 fp16 [hi | lo]
__device__ unsigned short g_ks  [(size_t)MM*2*DD];   // k     fp16 [hi | hi]
__device__ unsigned short g_vs  [(size_t)MM*DD];     // v     fp16 single

// ---------------------------------------------------------------------------
// Helpers
// ---------------------------------------------------------------------------
__device__ __forceinline__ uint32_t smem_u32(const void* p) {
    uint32_t a;
    asm("{ .reg .u64 t; cvta.to.shared.u64 t, %1; cvt.u32.u64 %0, t; }"
        : "=r"(a) : "l"(p));
    return a;
}

__device__ __forceinline__ void cp16(uint32_t dst, const void* src) {
    asm volatile("cp.async.cg.shared.global [%0], [%1], 16;" :: "r"(dst), "l"(src));
}

#define CP_COMMIT() asm volatile("cp.async.commit_group;")
#define CP_WAIT2()  asm volatile("cp.async.wait_group 2;" ::: "memory")

#define LDSM4(r0, r1, r2, r3, addr) \
    asm volatile("ldmatrix.sync.aligned.m8n8.x4.shared.b16 {%0,%1,%2,%3}, [%4];" \
        : "=r"(r0), "=r"(r1), "=r"(r2), "=r"(r3) : "r"(addr))

#define LDSM4T(r0, r1, r2, r3, addr) \
    asm volatile("ldmatrix.sync.aligned.m8n8.x4.trans.shared.b16 {%0,%1,%2,%3}, [%4];" \
        : "=r"(r0), "=r"(r1), "=r"(r2), "=r"(r3) : "r"(addr))

// fp16 MMA
#define MMA16816F(d, a, b0v, b1v) \
    asm volatile("mma.sync.aligned.m16n8k16.row.col.f32.f16.f16.f32 " \
        "{%0,%1,%2,%3}, {%4,%5,%6,%7}, {%8,%9}, {%0,%1,%2,%3};" \
        : "+f"((d)[0]), "+f"((d)[1]), "+f"((d)[2]), "+f"((d)[3]) \
        : "r"((a)[0]), "r"((a)[1]), "r"((a)[2]), "r"((a)[3]), "r"(b0v), "r"(b1v))

__device__ __forceinline__ unsigned short f2h_bits(float f) {
    __half h = __float2half(f);
    return *reinterpret_cast<unsigned short*>(&h);
}
__device__ __forceinline__ void hsplit(float x, unsigned short& h, unsigned short& l) {
    h = f2h_bits(x);
    __half hb = *reinterpret_cast<__half*>(&h);
    l = f2h_bits(x - __half2float(hb));
}

// ---------------------------------------------------------------------------
// fp32 -> fp16 single-term conversion for activations. A[m, K].
// ---------------------------------------------------------------------------
__global__ __launch_bounds__(256) void convert_a_kernel(
    const float* __restrict__ X, unsigned short* __restrict__ A, int K)
{
    size_t idx = (size_t)blockIdx.x * blockDim.x + threadIdx.x;
    size_t total = (size_t)MM * K / 4;
    if (idx >= total) return;
    size_t e = idx * 4;
    float4 v = *(const float4*)(X + e);
    uint2 hp = make_uint2((uint32_t)f2h_bits(v.x) | ((uint32_t)f2h_bits(v.y) << 16),
                          (uint32_t)f2h_bits(v.z) | ((uint32_t)f2h_bits(v.w) << 16));
    *(uint2*)(A + e) = hp;
}

// ---------------------------------------------------------------------------
// W[K,N] fp32 -> B[N, K] fp16 (transposed).
// ---------------------------------------------------------------------------
__global__ __launch_bounds__(256) void convert_w_kernel(
    const float* __restrict__ W, unsigned short* __restrict__ Bm, int K, int N)
{
    __shared__ float tile[32][33];
    const int n0 = blockIdx.x * 32;
    const int k0 = blockIdx.y * 32;
    for (int i = threadIdx.y; i < 32; i += 8)
        tile[i][threadIdx.x] = W[(size_t)(k0 + i) * N + n0 + threadIdx.x];
    __syncthreads();
    for (int i = threadIdx.y; i < 32; i += 8) {
        const int n = n0 + i;
        const int k = k0 + threadIdx.x;
        Bm[(size_t)n * K + k] = f2h_bits(tile[threadIdx.x][i]);
    }
}

// ---------------------------------------------------------------------------
// mma.sync fp16 GEMM: BM=BN=128, BK=32, 3-stage cp.async, 256 threads
// (8 warps 2x4, warp tile 64x32), __launch_bounds__(256, 2).
// C = A[M,K] @ B[N,K]^T + bias. Epilogue modes:
//   0: fp32 C = acc + bias                  -> Cf[m][N]
//   1: relu -> fp16                         -> Cs[m][N]
//   2: (acc+bias)*0.125 -> fp16 [hi|lo] [Q] -> Cs[m][2N]
//   3: fp16 [hi|hi]                     [K] -> Cs[m][2N]
//   4: fp16 single                      [V] -> Cs[m][N]
// ---------------------------------------------------------------------------
#define BK 32
#define NSTAGE 3
#define ROWB 80
#define B_OFF (128*ROWB)
#define STG_B (2*B_OFF)
#define GEMM_SMEM (NSTAGE*STG_B)    // 61440

__global__ __launch_bounds__(256, 2) void mma_gemm_kernel(
    const unsigned short* __restrict__ Au, const unsigned short* __restrict__ Bu,
    const float* __restrict__ bias, float* __restrict__ Cf,
    unsigned short* __restrict__ Cs, int N, int K2, int mode)
{
    extern __shared__ char smem[];
    const uint32_t sb = smem_u32(smem);
    const int tid = threadIdx.x;
    const int wid = tid >> 5, lane = tid & 31;
    const int wm = wid >> 2, wn = wid & 3;
    const int mb = blockIdx.y, nb = blockIdx.x;

    const int r0 = tid >> 2, cc = tid & 3;
    const unsigned short* aS = Au + ((size_t)(mb * 128) + r0) * K2 + cc * 8;
    const unsigned short* bS = Bu + ((size_t)(nb * 128) + r0) * K2 + cc * 8;
    const size_t rowskip = (size_t)64 * K2;
    const uint32_t dOff = (uint32_t)(r0 * ROWB + cc * 16);

    float acc[4][4][4];
    #pragma unroll
    for (int i = 0; i < 4; i++)
        #pragma unroll
        for (int j = 0; j < 4; j++)
            #pragma unroll
            for (int r = 0; r < 4; r++) acc[i][j][r] = 0.f;

    const int nc = K2 / BK;

    auto LOAD = [&](int s, int c) {
        const uint32_t d = sb + s * STG_B + dOff;
        const unsigned short* a = aS + (size_t)c * BK;
        const unsigned short* b = bS + (size_t)c * BK;
        cp16(d,                    a);
        cp16(d + 64 * ROWB,        a + rowskip);
        cp16(d + B_OFF,            b);
        cp16(d + B_OFF + 64*ROWB,  b + rowskip);
    };

    LOAD(0, 0); CP_COMMIT();
    LOAD(1, 1); CP_COMMIT();

    const uint32_t aRow = (uint32_t)(wm * 64 + (lane & 15));
    const uint32_t aK   = ((lane >> 4) & 1) * 16;
    const uint32_t bRow = (uint32_t)(wn * 32 + ((lane >> 4) & 1) * 8 + (lane & 7));
    const uint32_t bK   = ((lane >> 3) & 1) * 16;

    for (int c = 0; c < nc; c++) {
        if (c + 2 < nc) LOAD((c + 2) % NSTAGE, c + 2);
        CP_COMMIT();
        CP_WAIT2();
        __syncthreads();
        const uint32_t base = sb + (c % NSTAGE) * STG_B;
        #pragma unroll
        for (int ks = 0; ks < 2; ks++) {
            uint32_t af[4][4], bf[2][4];
            #pragma unroll
            for (int mt = 0; mt < 4; mt++) {
                const uint32_t ad = base + (aRow + mt * 16) * ROWB + ks * 32 + aK;
                LDSM4(af[mt][0], af[mt][1], af[mt][2], af[mt][3], ad);
            }
            #pragma unroll
            for (int j = 0; j < 2; j++) {
                const uint32_t bd = base + B_OFF + (bRow + j * 16) * ROWB + ks * 32 + bK;
                LDSM4(bf[j][0], bf[j][1], bf[j][2], bf[j][3], bd);
            }
            #pragma unroll
            for (int mt = 0; mt < 4; mt++)
                #pragma unroll
                for (int nt = 0; nt < 4; nt++)
                    MMA16816F(acc[mt][nt], af[mt],
                              bf[nt >> 1][(nt & 1) * 2], bf[nt >> 1][(nt & 1) * 2 + 1]);
        }
        __syncthreads();
    }

    // ---------------- epilogue (fused conversions) ----------------
    const int row0 = mb * 128 + wm * 64 + (lane >> 2);
    const int col0 = nb * 128 + wn * 32 + (lane & 3) * 2;
    #pragma unroll
    for (int mt = 0; mt < 4; mt++) {
        const int r1 = row0 + mt * 16;
        const int r2 = r1 + 8;
        #pragma unroll
        for (int nt = 0; nt < 4; nt++) {
            const int cn = col0 + nt * 8;
            const float bx = __ldg(bias + cn), by = __ldg(bias + cn + 1);
            float o10 = acc[mt][nt][0] + bx, o11 = acc[mt][nt][1] + by;
            float o20 = acc[mt][nt][2] + bx, o21 = acc[mt][nt][3] + by;
            if (mode == 0) {
                *(float2*)(Cf + (size_t)r1 * N + cn) = make_float2(o10, o11);
                *(float2*)(Cf + (size_t)r2 * N + cn) = make_float2(o20, o21);
            } else if (mode == 1) {
                o10 = fmaxf(o10, 0.f); o11 = fmaxf(o11, 0.f);
                o20 = fmaxf(o20, 0.f); o21 = fmaxf(o21, 0.f);
                *(uint32_t*)(Cs + (size_t)r1 * N + cn) =
                    (uint32_t)f2h_bits(o10) | ((uint32_t)f2h_bits(o11) << 16);
                *(uint32_t*)(Cs + (size_t)r2 * N + cn) =
                    (uint32_t)f2h_bits(o20) | ((uint32_t)f2h_bits(o21) << 16);
            } else if (mode == 4) {
                // V: fp16 single
                *(uint32_t*)(Cs + (size_t)r1 * N + cn) =
                    (uint32_t)f2h_bits(o10) | ((uint32_t)f2h_bits(o11) << 16);
                *(uint32_t*)(Cs + (size_t)r2 * N + cn) =
                    (uint32_t)f2h_bits(o20) | ((uint32_t)f2h_bits(o21) << 16);
            } else if (mode == 2) {
                // Q: *0.125 -> fp16 [hi | lo]
                o10 *= 0.125f; o11 *= 0.125f; o20 *= 0.125f; o21 *= 0.125f;
                unsigned short h0, l0, h1, l1;
                hsplit(o10, h0, l0); hsplit(o11, h1, l1);
                unsigned short* p = Cs + (size_t)r1 * (2 * N) + cn;
                *(uint32_t*)p       = (uint32_t)h0 | ((uint32_t)h1 << 16);
                *(uint32_t*)(p + N) = (uint32_t)l0 | ((uint32_t)l1 << 16);
                hsplit(o20, h0, l0); hsplit(o21, h1, l1);
                p = Cs + (size_t)r2 * (2 * N) + cn;
                *(uint32_t*)p       = (uint32_t)h0 | ((uint32_t)h1 << 16);
                *(uint32_t*)(p + N) = (uint32_t)l0 | ((uint32_t)l1 << 16);
            } else {
                // K (mode 3): fp16 [hi | hi]
                uint32_t w1v = (uint32_t)f2h_bits(o10) | ((uint32_t)f2h_bits(o11) << 16);
                unsigned short* p = Cs + (size_t)r1 * (2 * N) + cn;
                *(uint32_t*)p       = w1v;
                *(uint32_t*)(p + N) = w1v;
                uint32_t w2v = (uint32_t)f2h_bits(o20) | ((uint32_t)f2h_bits(o21) << 16);
                p = Cs + (size_t)r2 * (2 * N) + cn;
                *(uint32_t*)p       = w2v;
                *(uint32_t*)(p + N) = w2v;
            }
        }
    }
}

// ---------------------------------------------------------------------------
// Tensor-core flash attention, fp16 2-term. Inputs PRE-SPLIT:
//   Qg [m][2D]: fp16 [hi|lo] scaled 1/8; Kg [m][2D]: fp16 [hi|hi];
//   Vg [m][D]: fp16 single.
// S = (Qhi+Qlo)·Khi via 2-term K''=128; P = [hi|lo] fp16; O += Phi·V + Plo·V.
// Softmax in fp32. Epilogue writes fp16 single into g_aatt[m][D].
// ---------------------------------------------------------------------------
#define AQROWB 272                      // 128 fp16 data + 8 pad  (272%128==16)
#define AVROWB 144                      // 64 fp16 data + 8 pad
#define ATT2_SMEM (2*64*AQROWB + 64*AVROWB)   // 44032

__global__ __launch_bounds__(128, 2) void attn_tc_kernel(
    const unsigned short* __restrict__ Qg, const unsigned short* __restrict__ Kg,
    const unsigned short* __restrict__ Vg, unsigned short* __restrict__ Aout)
{
    extern __shared__ char sm8[];
    char* Qs = sm8;
    char* Ks = Qs + 64 * AQROWB;
    char* Vs = Ks + 64 * AQROWB;
    const uint32_t qsb = smem_u32(Qs), ksb = smem_u32(Ks);
    const uint32_t vsb = smem_u32(Vs);

    const int tid = threadIdx.x, wid = tid >> 5, lane = tid & 31;
    const int q0 = blockIdx.x * 64;
    const int b = blockIdx.y >> 4, h = blockIdx.y & 15;
    const size_t bS = (size_t)b * SS;

    // ---- load Q tile: row = [hi(64) | lo(64)] fp16, 2 threads/row ----
    {
        const int r = tid >> 1, half = tid & 1;
        const unsigned short* src = Qg + (bS + q0 + r) * (size_t)(2 * DD)
                                       + half * DD + h * 64;
        char* drow = Qs + r * AQROWB + half * 128;
        #pragma unroll
        for (int off = 0; off < 8; off++)
            *(uint4*)(drow + off * 16) = *(const uint4*)(src + off * 8);
    }
    __syncthreads();

    // ---- Q fragments (8 k-steps x 4 regs) ----
    uint32_t qf[8][4];
    {
        const uint32_t ab = qsb + (wid * 16 + (lane & 15)) * AQROWB + ((lane >> 4) & 1) * 16;
        #pragma unroll
        for (int ks = 0; ks < 8; ks++)
            LDSM4(qf[ks][0], qf[ks][1], qf[ks][2], qf[ks][3], ab + ks * 32);
    }

    const uint32_t bRow = ((lane >> 4) & 1) * 8 + (lane & 7);
    const uint32_t bK   = ((lane >> 3) & 1) * 16;
    const uint32_t vLn  = (lane & 15);
    const uint32_t vCo  = ((lane >> 4) & 1) * 16;

    float O[8][4];
    #pragma unroll
    for (int j = 0; j < 8; j++)
        #pragma unroll
        for (int r = 0; r < 4; r++) O[j][r] = 0.f;
    float m0 = -1e30f, m1 = -1e30f, l0 = 0.f, l1 = 0.f;

    const int r0l = wid * 16 + (lane >> 2);
    const int r1l = r0l + 8;

    for (int kt = 0; kt <= blockIdx.x; kt++) {
        const int k0 = kt * 64;
        __syncthreads();
        // ---- load K tile (2 thr/row, 8 chunks) + V tile (2 thr/row, 4 chunks) ----
        {
            const int r = tid >> 1, half = tid & 1;
            const unsigned short* ksrc = Kg + (bS + k0 + r) * (size_t)(2 * DD)
                                            + half * DD + h * 64;
            char* krow = Ks + r * AQROWB + half * 128;
            #pragma unroll
            for (int off = 0; off < 8; off++)
                *(uint4*)(krow + off * 16) = *(const uint4*)(ksrc + off * 8);
            const unsigned short* vsrc = Vg + (bS + k0 + r) * (size_t)DD
                                            + h * 64 + half * 32;
            char* vrow = Vs + r * AVROWB + half * 64;
            #pragma unroll
            for (int off = 0; off < 4; off++)
                *(uint4*)(vrow + off * 16) = *(const uint4*)(vsrc + off * 8);
        }
        __syncthreads();

        // ---- S = Q'' K''^T (fp16, K''=128) ----
        float s[8][4];
        #pragma unroll
        for (int j = 0; j < 8; j++)
            #pragma unroll
            for (int r = 0; r < 4; r++) s[j][r] = 0.f;
        #pragma unroll
        for (int ks = 0; ks < 8; ks++) {
            #pragma unroll
            for (int j16 = 0; j16 < 4; j16++) {
                uint32_t kf0, kf1, kf2, kf3;
                LDSM4(kf0, kf1, kf2, kf3,
                      ksb + (j16 * 16 + bRow) * AQROWB + ks * 32 + bK);
                MMA16816F(s[2 * j16],     qf[ks], kf0, kf1);
                MMA16816F(s[2 * j16 + 1], qf[ks], kf2, kf3);
            }
        }

        // ---- causal mask (diagonal tile only) ----
        if (kt == (int)blockIdx.x) {
            #pragma unroll
            for (int j = 0; j < 8; j++) {
                const int c = j * 8 + 2 * (lane & 3);
                if (c     > r0l) s[j][0] = -1e30f;
                if (c + 1 > r0l) s[j][1] = -1e30f;
                if (c     > r1l) s[j][2] = -1e30f;
                if (c + 1 > r1l) s[j][3] = -1e30f;
            }
        }

        // ---- online softmax ----
        float mx0 = -1e30f, mx1 = -1e30f;
        #pragma unroll
        for (int j = 0; j < 8; j++) {
            mx0 = fmaxf(mx0, fmaxf(s[j][0], s[j][1]));
            mx1 = fmaxf(mx1, fmaxf(s[j][2], s[j][3]));
        }
        mx0 = fmaxf(mx0, __shfl_xor_sync(0xffffffffu, mx0, 1));
        mx0 = fmaxf(mx0, __shfl_xor_sync(0xffffffffu, mx0, 2));
        mx1 = fmaxf(mx1, __shfl_xor_sync(0xffffffffu, mx1, 1));
        mx1 = fmaxf(mx1, __shfl_xor_sync(0xffffffffu, mx1, 2));
        const float mn0 = fmaxf(m0, mx0), mn1 = fmaxf(m1, mx1);
        const float cr0 = __expf(m0 - mn0), cr1 = __expf(m1 - mn1);
        m0 = mn0; m1 = mn1;
        float sum0 = 0.f, sum1 = 0.f;
        #pragma unroll
        for (int j = 0; j < 8; j++) {
            s[j][0] = __expf(s[j][0] - mn0);
            s[j][1] = __expf(s[j][1] - mn0);
            s[j][2] = __expf(s[j][2] - mn1);
            s[j][3] = __expf(s[j][3] - mn1);
            sum0 += s[j][0] + s[j][1];
            sum1 += s[j][2] + s[j][3];
        }
        sum0 += __shfl_xor_sync(0xffffffffu, sum0, 1);
        sum0 += __shfl_xor_sync(0xffffffffu, sum0, 2);
        sum1 += __shfl_xor_sync(0xffffffffu, sum1, 1);
        sum1 += __shfl_xor_sync(0xffffffffu, sum1, 2);
        l0 = l0 * cr0 + sum0;
        l1 = l1 * cr1 + sum1;
        #pragma unroll
        for (int j = 0; j < 8; j++) {
            O[j][0] *= cr0; O[j][1] *= cr0;
            O[j][2] *= cr1; O[j][3] *= cr1;
        }

        // ---- P -> fp16 hi/lo A-fragments ----
        uint32_t phi[4][4], plo[4][4];
        #pragma unroll
        for (int ks2 = 0; ks2 < 4; ks2++) {
            const int j0 = 2 * ks2, j1 = j0 + 1;
            unsigned short h00, l00, h01, l01, h10, l10, h11, l11;
            hsplit(s[j0][0], h00, l00); hsplit(s[j0][1], h01, l01);
            phi[ks2][0] = (uint32_t)h00 | ((uint32_t)h01 << 16);
            plo[ks2][0] = (uint32_t)l00 | ((uint32_t)l01 << 16);
            hsplit(s[j0][2], h10, l10); hsplit(s[j0][3], h11, l11);
            phi[ks2][1] = (uint32_t)h10 | ((uint32_t)h11 << 16);
            plo[ks2][1] = (uint32_t)l10 | ((uint32_t)l11 << 16);
            hsplit(s[j1][0], h00, l00); hsplit(s[j1][1], h01, l01);
            phi[ks2][2] = (uint32_t)h00 | ((uint32_t)h01 << 16);
            plo[ks2][2] = (uint32_t)l00 | ((uint32_t)l01 << 16);
            hsplit(s[j1][2], h10, l10); hsplit(s[j1][3], h11, l11);
            phi[ks2][3] = (uint32_t)h10 | ((uint32_t)h11 << 16);
            plo[ks2][3] = (uint32_t)l10 | ((uint32_t)l11 << 16);
        }

        // ---- O += Phi*V + Plo*V ----
        #pragma unroll
        for (int ks2 = 0; ks2 < 4; ks2++) {
            const uint32_t rowOff = (ks2 * 16 + vLn);
            #pragma unroll
            for (int dj = 0; dj < 4; dj++) {
                uint32_t v0, v1, v2, v3;
                LDSM4T(v0, v1, v2, v3, vsb + rowOff * AVROWB + dj * 32 + vCo);
                MMA16816F(O[2 * dj],     phi[ks2], v0, v1);
                MMA16816F(O[2 * dj + 1], phi[ks2], v2, v3);
                MMA16816F(O[2 * dj],     plo[ks2], v0, v1);
                MMA16816F(O[2 * dj + 1], plo[ks2], v2, v3);
            }
        }
    }

    // ---- epilogue: O/l -> fp16 single rows of g_aatt ----
    const float inv0 = 1.f / l0, inv1 = 1.f / l1;
    const size_t m0g = bS + (q0 + r0l);
    const size_t m1g = m0g + 8;
    const int cb = h * 64 + 2 * (lane & 3);
    unsigned short* out0 = Aout + m0g * (size_t)DD + cb;
    unsigned short* out1 = Aout + m1g * (size_t)DD + cb;
    #pragma unroll
    for (int j = 0; j < 8; j++) {
        const int d = j * 8;
        *(uint32_t*)(out0 + d) = (uint32_t)f2h_bits(O[j][0] * inv0)
                               | ((uint32_t)f2h_bits(O[j][1] * inv0) << 16);
        *(uint32_t*)(out1 + d) = (uint32_t)f2h_bits(O[j][2] * inv1)
                               | ((uint32_t)f2h_bits(O[j][3] * inv1) << 16);
    }
}

// ---------------------------------------------------------------------------
// out = LayerNorm(x + y) * gamma + beta; optional fused fp16 conversion
// ---------------------------------------------------------------------------
__device__ __forceinline__ float block_sum(float v, float* sh)
{
    const int lane = threadIdx.x & 31, w = threadIdx.x >> 5;
    #pragma unroll
    for (int o = 16; o; o >>= 1) v += __shfl_xor_sync(0xffffffffu, v, o);
    if (lane == 0) sh[w] = v;
    __syncthreads();
    float r = (lane < 8) ? sh[lane] : 0.f;
    #pragma unroll
    for (int o = 4; o; o >>= 1) r += __shfl_xor_sync(0xffffffffu, r, o);
    if (threadIdx.x == 0) sh[0] = r;
    __syncthreads();
    r = sh[0];
    __syncthreads();
    return r;
}

__global__ __launch_bounds__(256) void add_ln_kernel(
    const float* __restrict__ X, const float* __restrict__ Y,
    const float* __restrict__ g, const float* __restrict__ bta,
    float* __restrict__ out, unsigned short* __restrict__ As)
{
    __shared__ float sh[32];
    const size_t row = blockIdx.x;
    const int t = threadIdx.x;
    const float4 xv = ((const float4*)(X + row * DD))[t];
    const float4 yv = ((const float4*)(Y + row * DD))[t];
    float v0 = xv.x + yv.x, v1 = xv.y + yv.y, v2 = xv.z + yv.z, v3 = xv.w + yv.w;
    const float mean = block_sum(v0 + v1 + v2 + v3, sh) * (1.f / DD);
    const float d0 = v0 - mean, d1 = v1 - mean, d2 = v2 - mean, d3 = v3 - mean;
    const float var = block_sum(d0*d0 + d1*d1 + d2*d2 + d3*d3, sh) * (1.f / DD);
    const float inv = rsqrtf(var + 1e-5f);
    const float4 gv = ((const float4*)g)[t];
    const float4 bv = ((const float4*)bta)[t];
    float4 o;
    o.x = d0 * inv * gv.x + bv.x;
    o.y = d1 * inv * gv.y + bv.y;
    o.z = d2 * inv * gv.z + bv.z;
    o.w = d3 * inv * gv.w + bv.w;
    ((float4*)(out + row * DD))[t] = o;
    if (As) {
        uint2 hp = make_uint2((uint32_t)f2h_bits(o.x) | ((uint32_t)f2h_bits(o.y) << 16),
                              (uint32_t)f2h_bits(o.z) | ((uint32_t)f2h_bits(o.w) << 16));
        *(uint2*)(As + row * (size_t)DD + t * 4) = hp;
    }
}

// ---------------------------------------------------------------------------
// Launcher
// ---------------------------------------------------------------------------
extern "C" void kernel_launch(void* const* d_in, const int* in_sizes, int n_in,
                              void* d_out, int out_size)
{
    (void)in_sizes; (void)n_in; (void)out_size;
    const float* x  = (const float*)d_in[0];
    const float* Wq = (const float*)d_in[2];
    const float* bq = (const float*)d_in[3];
    const float* Wk = (const float*)d_in[4];
    const float* bk = (const float*)d_in[5];
    const float* Wv = (const float*)d_in[6];
    const float* bv = (const float*)d_in[7];
    const float* Wo = (const float*)d_in[8];
    const float* bo = (const float*)d_in[9];
    const float* g1 = (const float*)d_in[10];
    const float* b1 = (const float*)d_in[11];
    const float* W1 = (const float*)d_in[12];
    const float* c1 = (const float*)d_in[13];
    const float* W2 = (const float*)d_in[14];
    const float* c2 = (const float*)d_in[15];
    const float* g2 = (const float*)d_in[16];
    const float* b2 = (const float*)d_in[17];
    float* out = (float*)d_out;

    float *proj, *x1, *ff2;
    cudaGetSymbolAddress((void**)&proj, g_proj);
    cudaGetSymbolAddress((void**)&x1,   g_x1);
    cudaGetSymbolAddress((void**)&ff2,  g_ff2);

    unsigned short *ax, *qs, *ks, *vs, *aatt, *ax1, *aff1;
    unsigned short *wq2, *wk2, *wv2, *wo2, *w12, *w22;
    cudaGetSymbolAddress((void**)&ax,   g_ax);
    cudaGetSymbolAddress((void**)&qs,   g_qs);
    cudaGetSymbolAddress((void**)&ks,   g_ks);
    cudaGetSymbolAddress((void**)&vs,   g_vs);
    cudaGetSymbolAddress((void**)&aatt, g_aatt);
    cudaGetSymbolAddress((void**)&ax1,  g_ax1);
    cudaGetSymbolAddress((void**)&aff1, g_aff1);
    cudaGetSymbolAddress((void**)&wq2,  g_wq);
    cudaGetSymbolAddress((void**)&wk2,  g_wk);
    cudaGetSymbolAddress((void**)&wv2,  g_wv);
    cudaGetSymbolAddress((void**)&wo2,  g_wo);
    cudaGetSymbolAddress((void**)&w12,  g_w1);
    cudaGetSymbolAddress((void**)&w22,  g_w2);

    cudaFuncSetAttribute(mma_gemm_kernel,
                         cudaFuncAttributeMaxDynamicSharedMemorySize, GEMM_SMEM);
    cudaFuncSetAttribute(attn_tc_kernel,
                         cudaFuncAttributeMaxDynamicSharedMemorySize, ATT2_SMEM);

    const dim3 blk(256);
    const dim3 wblk(32, 8);
    const dim3 gD(DD/128, MM/128);       // N=1024 GEMMs
    const dim3 gF(FF/128, MM/128);       // N=4096 GEMM

    convert_w_kernel<<<dim3(DD/32, DD/32), wblk>>>(Wq, wq2, DD, DD);
    convert_w_kernel<<<dim3(DD/32, DD/32), wblk>>>(Wk, wk2, DD, DD);
    convert_w_kernel<<<dim3(DD/32, DD/32), wblk>>>(Wv, wv2, DD, DD);
    convert_w_kernel<<<dim3(DD/32, DD/32), wblk>>>(Wo, wo2, DD, DD);
    convert_a_kernel<<<(int)(((size_t)MM*DD/4 + 255)/256), blk>>>(x, ax, DD);

    // QKV projections -> fp16 attention layouts
    mma_gemm_kernel<<<gD, blk, GEMM_SMEM>>>(ax, wq2, bq, nullptr, qs, DD, DD, 2);
    mma_gemm_kernel<<<gD, blk, GEMM_SMEM>>>(ax, wk2, bk, nullptr, ks, DD, DD, 3);
    mma_gemm_kernel<<<gD, blk, GEMM_SMEM>>>(ax, wv2, bv, nullptr, vs, DD, DD, 4);

    // attention (fp16 2-term, writes fp16 single A)
    attn_tc_kernel<<<dim3(SS/64, BB*HH), 128, ATT2_SMEM>>>(qs, ks, vs, aatt);

    // output projection + residual LN (fused fp16 conversion of x1)
    mma_gemm_kernel<<<gD, blk, GEMM_SMEM>>>(aatt, wo2, bo, proj, nullptr, DD, DD, 0);
    add_ln_kernel<<<MM, blk>>>(x, proj, g1, b1, x1, ax1);

    // FFN
    convert_w_kernel<<<dim3(FF/32, DD/32), wblk>>>(W1, w12, DD, FF);
    mma_gemm_kernel<<<gF, blk, GEMM_SMEM>>>(ax1, w12, c1, nullptr, aff1, FF, DD, 1);
    convert_w_kernel<<<dim3(DD/32, FF/32), wblk>>>(W2, w22, FF, DD);
    mma_gemm_kernel<<<gD, blk, GEMM_SMEM>>>(aff1, w22, c2, ff2, nullptr, DD, FF, 0);
    add_ln_kernel<<<MM, blk>>>(x1, ff2, g2, b2, out, nullptr);
}